// round 10
// baseline (speedup 1.0000x reference)
#include <cuda_runtime.h>
#include <cuda_bf16.h>
#include <cstdint>
#include <math.h>

#define BB 2
#define TT 2048
#define DD 1024
#define HH 16
#define HDIM 64
#define MROWS (BB * TT)   // 4096

// ---------------------------------------------------------------------------
// Scratch (device globals; no allocation anywhere)
// ---------------------------------------------------------------------------
__device__ __align__(256) __nv_bfloat16 g_xh[(size_t)MROWS * DD];
__device__ __align__(256) __nv_bfloat16 g_xl[(size_t)MROWS * DD];
__device__ __align__(256) __nv_bfloat16 g_wqh[(size_t)3 * DD * DD];
__device__ __align__(256) __nv_bfloat16 g_wql[(size_t)3 * DD * DD];
__device__ __align__(256) __nv_bfloat16 g_wph[(size_t)DD * DD];
__device__ __align__(256) __nv_bfloat16 g_wpl[(size_t)DD * DD];
__device__ __align__(256) __nv_bfloat16 g_yh[(size_t)MROWS * DD];
__device__ __align__(256) __nv_bfloat16 g_yl[(size_t)MROWS * DD];
// q/k/v in [b,h,t,d] layout, hi/lo bf16
__device__ __align__(256) __nv_bfloat16 g_qh[(size_t)MROWS * DD];
__device__ __align__(256) __nv_bfloat16 g_ql[(size_t)MROWS * DD];
__device__ __align__(256) __nv_bfloat16 g_kh[(size_t)MROWS * DD];
__device__ __align__(256) __nv_bfloat16 g_kl[(size_t)MROWS * DD];
__device__ __align__(256) __nv_bfloat16 g_vh[(size_t)MROWS * DD];
__device__ __align__(256) __nv_bfloat16 g_vl[(size_t)MROWS * DD];

// ---------------------------------------------------------------------------
// helpers
// ---------------------------------------------------------------------------
__device__ __forceinline__ uint32_t smem_u32(const void* p) {
    uint32_t a;
    asm("{ .reg .u64 t; cvta.to.shared.u64 t, %1; cvt.u32.u64 %0, t; }"
        : "=r"(a) : "l"(p));
    return a;
}
__device__ __forceinline__ void cp16(uint32_t d, const void* g) {
    asm volatile("cp.async.cg.shared.global [%0], [%1], 16;" :: "r"(d), "l"(g));
}
__device__ __forceinline__ void ldsm4(uint32_t* r, uint32_t a) {
    asm volatile("ldmatrix.sync.aligned.m8n8.x4.shared.b16 {%0,%1,%2,%3}, [%4];"
        : "=r"(r[0]), "=r"(r[1]), "=r"(r[2]), "=r"(r[3]) : "r"(a));
}
__device__ __forceinline__ void ldsm4t(uint32_t* r, uint32_t a) {
    asm volatile("ldmatrix.sync.aligned.m8n8.x4.trans.shared.b16 {%0,%1,%2,%3}, [%4];"
        : "=r"(r[0]), "=r"(r[1]), "=r"(r[2]), "=r"(r[3]) : "r"(a));
}
__device__ __forceinline__ void mma16816(float* c, const uint32_t* a, const uint32_t* b) {
    asm volatile("mma.sync.aligned.m16n8k16.row.col.f32.bf16.bf16.f32 "
        "{%0,%1,%2,%3}, {%4,%5,%6,%7}, {%8,%9}, {%0,%1,%2,%3};"
        : "+f"(c[0]), "+f"(c[1]), "+f"(c[2]), "+f"(c[3])
        : "r"(a[0]), "r"(a[1]), "r"(a[2]), "r"(a[3]), "r"(b[0]), "r"(b[1]));
}
__device__ __forceinline__ uint32_t bfpack(float lo, float hi) {
    uint32_t r;
    asm("cvt.rn.bf16x2.f32 %0, %1, %2;" : "=r"(r) : "f"(hi), "f"(lo));
    return r;
}
__device__ __forceinline__ void split_pack(float v0, float v1, uint32_t& hp, uint32_t& lp) {
    __nv_bfloat16 h0 = __float2bfloat16(v0), h1 = __float2bfloat16(v1);
    hp = ((uint32_t)__bfloat16_as_ushort(h1) << 16) | (uint32_t)__bfloat16_as_ushort(h0);
    lp = bfpack(v0 - __bfloat162float(h0), v1 - __bfloat162float(h1));
}
#define CP_COMMIT() asm volatile("cp.async.commit_group;" ::: "memory")
#define CP_WAIT1()  asm volatile("cp.async.wait_group 1;" ::: "memory")
#define CP_WAIT2()  asm volatile("cp.async.wait_group 2;" ::: "memory")

// ---------------------------------------------------------------------------
// fp32 -> bf16 hi/lo split (inputs)
// ---------------------------------------------------------------------------
__global__ __launch_bounds__(256) void split_kernel(const float* __restrict__ in,
                                                    __nv_bfloat16* __restrict__ hi,
                                                    __nv_bfloat16* __restrict__ lo,
                                                    int n4) {
    int i = blockIdx.x * blockDim.x + threadIdx.x;
    if (i >= n4) return;
    float4 v = ((const float4*)in)[i];
    uint32_t h0, l0, h1, l1;
    split_pack(v.x, v.y, h0, l0);
    split_pack(v.z, v.w, h1, l1);
    ((uint32_t*)hi)[2 * i] = h0; ((uint32_t*)hi)[2 * i + 1] = h1;
    ((uint32_t*)lo)[2 * i] = l0; ((uint32_t*)lo)[2 * i + 1] = l1;
}

// ---------------------------------------------------------------------------
// Fused 3-term bf16x3 GEMM: C = Ah*(Bh+Bl) + Al*Bh (+bias)
// GS=4 pipeline of BK=16 stages: stage = {Ah,Al,Bh,Bl} 128x16 tiles at 48B
// pitch (rows 0..7 at fixed chunk hit 8 distinct bank groups). 24KB/stage,
// 96KB total -> 2 CTA/SM. Refill issued BEFORE compute (free 4th slot).
// Term-major MMA ordering: RAW reuse distance 8.
// ---------------------------------------------------------------------------
#define TILE_B (128 * 48)       // 6144
#define STAGE4_B (4 * TILE_B)   // 24576
#define NIT 64

__device__ __forceinline__ void load_stage4(uint32_t st,
                                            const __nv_bfloat16* __restrict__ Ah,
                                            const __nv_bfloat16* __restrict__ Al,
                                            const __nv_bfloat16* __restrict__ Bh,
                                            const __nv_bfloat16* __restrict__ Bl,
                                            int m0, int n0, int kk, int tid) {
    const int row = tid >> 1;           // 0..127
    const int ch  = tid & 1;            // 16B chunk within 32B row
    const uint32_t off = row * 48 + ch * 16;
    const size_t ga = (size_t)(m0 + row) * DD + kk + ch * 8;
    const size_t gb = (size_t)(n0 + row) * DD + kk + ch * 8;
    cp16(st + off,              Ah + ga);
    cp16(st + TILE_B + off,     Al + ga);
    cp16(st + 2 * TILE_B + off, Bh + gb);
    cp16(st + 3 * TILE_B + off, Bl + gb);
}

__device__ __forceinline__ void gemm_mainloop(uint32_t sbase,
                                              const __nv_bfloat16* __restrict__ Ah,
                                              const __nv_bfloat16* __restrict__ Al,
                                              const __nv_bfloat16* __restrict__ Bh,
                                              const __nv_bfloat16* __restrict__ Bl,
                                              int m0, int n0, int tid,
                                              float (&acc)[2][8][4]) {
    const int lane = tid & 31;
    const int warp = tid >> 5;
    const int wm = warp >> 1;
    const int wn = warp & 1;
    const int l_sub = lane & 15;
    const int l_cc  = lane >> 4;

    // prologue: 3 stages in flight
    load_stage4(sbase,                Ah, Al, Bh, Bl, m0, n0, 0,  tid); CP_COMMIT();
    load_stage4(sbase + STAGE4_B,     Ah, Al, Bh, Bl, m0, n0, 16, tid); CP_COMMIT();
    load_stage4(sbase + 2 * STAGE4_B, Ah, Al, Bh, Bl, m0, n0, 32, tid); CP_COMMIT();

    for (int it = 0; it < NIT; it++) {
        CP_WAIT2();                  // stage `it` landed
        __syncthreads();             // all warps done with stage it-1 (slot to refill)

        if (it + 3 < NIT)
            load_stage4(sbase + ((it + 3) & 3) * STAGE4_B,
                        Ah, Al, Bh, Bl, m0, n0, (it + 3) << 4, tid);
        CP_COMMIT();

        const uint32_t st = sbase + (it & 3) * STAGE4_B;

        uint32_t ah[2][4], al[2][4];
        #pragma unroll
        for (int i = 0; i < 2; i++) {
            const uint32_t ro = (wm * 32 + i * 16 + l_sub) * 48 + l_cc * 16;
            ldsm4(ah[i], st + ro);
            ldsm4(al[i], st + TILE_B + ro);
        }
        #pragma unroll
        for (int jh = 0; jh < 2; jh++) {
            uint32_t bh[4][2], bl[4][2];
            #pragma unroll
            for (int j2 = 0; j2 < 2; j2++) {
                const uint32_t ro = (wn * 64 + jh * 32 + j2 * 16 + l_sub) * 48 + l_cc * 16;
                uint32_t r[4];
                ldsm4(r, st + 2 * TILE_B + ro);
                bh[j2 * 2][0] = r[0];     bh[j2 * 2][1] = r[2];
                bh[j2 * 2 + 1][0] = r[1]; bh[j2 * 2 + 1][1] = r[3];
                ldsm4(r, st + 3 * TILE_B + ro);
                bl[j2 * 2][0] = r[0];     bl[j2 * 2][1] = r[2];
                bl[j2 * 2 + 1][0] = r[1]; bl[j2 * 2 + 1][1] = r[3];
            }
            // term-major: 8 independent accumulators between RAW reuse
            #pragma unroll
            for (int i = 0; i < 2; i++)
                #pragma unroll
                for (int j = 0; j < 4; j++) mma16816(acc[i][jh * 4 + j], ah[i], bh[j]);
            #pragma unroll
            for (int i = 0; i < 2; i++)
                #pragma unroll
                for (int j = 0; j < 4; j++) mma16816(acc[i][jh * 4 + j], ah[i], bl[j]);
            #pragma unroll
            for (int i = 0; i < 2; i++)
                #pragma unroll
                for (int j = 0; j < 4; j++) mma16816(acc[i][jh * 4 + j], al[i], bh[j]);
        }
    }
}

// ---- qkv GEMM: scatter epilogue -> q/k/v hi/lo in [b,h,t,d] (q scaled) ----
__global__ __launch_bounds__(256, 2)
void qkv_gemm_kernel(const __nv_bfloat16* __restrict__ Ah,
                     const __nv_bfloat16* __restrict__ Al,
                     const __nv_bfloat16* __restrict__ Bh,
                     const __nv_bfloat16* __restrict__ Bl,
                     const float* __restrict__ bias,
                     __nv_bfloat16* __restrict__ qh, __nv_bfloat16* __restrict__ ql,
                     __nv_bfloat16* __restrict__ kh, __nv_bfloat16* __restrict__ kl,
                     __nv_bfloat16* __restrict__ vh, __nv_bfloat16* __restrict__ vl) {
    extern __shared__ __align__(1024) char sm[];
    const uint32_t sbase = smem_u32(sm);
    const int tid = threadIdx.x;
    const int lane = tid & 31;
    const int warp = tid >> 5;
    const int wm = warp >> 1, wn = warp & 1;
    const int m0 = blockIdx.y * 128;
    const int n0 = blockIdx.x * 128;

    float acc[2][8][4];
    #pragma unroll
    for (int i = 0; i < 2; i++)
        #pragma unroll
        for (int j = 0; j < 8; j++)
            #pragma unroll
            for (int r = 0; r < 4; r++) acc[i][j][r] = 0.f;

    gemm_mainloop(sbase, Ah, Al, Bh, Bl, m0, n0, tid, acc);

    const int l4 = lane >> 2;
    const int l2 = (lane & 3) << 1;
    #pragma unroll
    for (int i = 0; i < 2; i++) {
        const int row = m0 + wm * 32 + i * 16 + l4;   // token index
        const int bi = row >> 11;
        const int t  = row & 2047;
        #pragma unroll
        for (int j = 0; j < 8; j++) {
            const int col = n0 + wn * 64 + j * 8 + l2;
            const int type = col >> 10;
            const int hc = (col & 1023) >> 6;
            const int d  = col & 63;
            const float2 bv = *(const float2*)(bias + col);
            float v0 = acc[i][j][0] + bv.x, v1 = acc[i][j][1] + bv.y;
            float v2 = acc[i][j][2] + bv.x, v3 = acc[i][j][3] + bv.y;
            if (type == 0) { v0 *= 0.125f; v1 *= 0.125f; v2 *= 0.125f; v3 *= 0.125f; }
            __nv_bfloat16* dh = (type == 0) ? qh : (type == 1) ? kh : vh;
            __nv_bfloat16* dl = (type == 0) ? ql : (type == 1) ? kl : vl;
            const size_t off0 = (((size_t)(bi * HH + hc)) * TT + t) * 64 + d;
            const size_t off1 = off0 + 8 * 64;
            uint32_t hp, lp;
            split_pack(v0, v1, hp, lp);
            ((uint32_t*)dh)[off0 >> 1] = hp; ((uint32_t*)dl)[off0 >> 1] = lp;
            split_pack(v2, v3, hp, lp);
            ((uint32_t*)dh)[off1 >> 1] = hp; ((uint32_t*)dl)[off1 >> 1] = lp;
        }
    }
}

// ---- proj GEMM: fp32 epilogue ----
__global__ __launch_bounds__(256, 2)
void proj_gemm_kernel(const __nv_bfloat16* __restrict__ Ah,
                      const __nv_bfloat16* __restrict__ Al,
                      const __nv_bfloat16* __restrict__ Bh,
                      const __nv_bfloat16* __restrict__ Bl,
                      const float* __restrict__ bias,
                      float* __restrict__ C, int ldc) {
    extern __shared__ __align__(1024) char sm[];
    const uint32_t sbase = smem_u32(sm);
    const int tid = threadIdx.x;
    const int lane = tid & 31;
    const int warp = tid >> 5;
    const int wm = warp >> 1, wn = warp & 1;
    const int m0 = blockIdx.y * 128;
    const int n0 = blockIdx.x * 128;

    float acc[2][8][4];
    #pragma unroll
    for (int i = 0; i < 2; i++)
        #pragma unroll
        for (int j = 0; j < 8; j++)
            #pragma unroll
            for (int r = 0; r < 4; r++) acc[i][j][r] = 0.f;

    gemm_mainloop(sbase, Ah, Al, Bh, Bl, m0, n0, tid, acc);

    const int l4 = lane >> 2;
    const int l2 = (lane & 3) << 1;
    #pragma unroll
    for (int i = 0; i < 2; i++) {
        const int row0 = m0 + wm * 32 + i * 16 + l4;
        #pragma unroll
        for (int j = 0; j < 8; j++) {
            const int col = n0 + wn * 64 + j * 8 + l2;
            const float2 bv = *(const float2*)(bias + col);
            float2 v0, v1;
            v0.x = acc[i][j][0] + bv.x; v0.y = acc[i][j][1] + bv.y;
            v1.x = acc[i][j][2] + bv.x; v1.y = acc[i][j][3] + bv.y;
            *(float2*)(C + (size_t)row0 * ldc + col) = v0;
            *(float2*)(C + (size_t)(row0 + 8) * ldc + col) = v1;
        }
    }
}

// ---------------------------------------------------------------------------
// Flash attention on mma.sync (bf16x3). CTA = 256 q rows x (head, batch),
// 512 threads = 16 warps (16 warps/SM for latency hiding; 147KB smem).
// Per-warp logic identical to the R7-validated kernel.
// ---------------------------------------------------------------------------
#define AP 144
#define Q2_BYTES (256 * AP)          // 36864 per Q component
#define KV_TILE_B (64 * AP)          // 9216
#define KV_STAGE_B (4 * KV_TILE_B)   // 36864
#define ATT_SMEM (2 * Q2_BYTES + 2 * KV_STAGE_B)  // 147456

__global__ __launch_bounds__(512, 1)
void attn_mma_kernel(const __nv_bfloat16* __restrict__ qh, const __nv_bfloat16* __restrict__ ql,
                     const __nv_bfloat16* __restrict__ kh, const __nv_bfloat16* __restrict__ kl,
                     const __nv_bfloat16* __restrict__ vh, const __nv_bfloat16* __restrict__ vl,
                     __nv_bfloat16* __restrict__ yh, __nv_bfloat16* __restrict__ yl) {
    extern __shared__ __align__(1024) char sm[];
    const uint32_t sb = smem_u32(sm);

    const int qi = blockIdx.x;           // 0..7
    const int h  = blockIdx.y;
    const int b  = blockIdx.z;
    const int q0 = qi * 256;
    const size_t base = ((size_t)(b * HH + h)) * TT * 64;

    const int tid  = threadIdx.x;
    const int warp = tid >> 5;           // 0..15
    const int lane = tid & 31;
    const int l_sub = lane & 15;
    const int l_cc  = lane >> 4;
    const int lq = lane >> 2;
    const int lr = lane & 3;

    // ---- stage Q (256 rows, hi+lo) ----
    #pragma unroll
    for (int t2 = 0; t2 < 4; t2++) {
        const int idx = tid + t2 * 512;  // 0..2047
        const int row = idx >> 3, ch = idx & 7;
        const uint32_t off = row * AP + ch * 16;
        const size_t g = base + (size_t)(q0 + row) * 64 + ch * 8;
        cp16(sb + off, qh + g);
        cp16(sb + Q2_BYTES + off, ql + g);
    }
    CP_COMMIT();

    const int nt = 4 * qi + 4;
    auto load_kv = [&](int s, int k0) {
        const uint32_t st = sb + 2 * Q2_BYTES + s * KV_STAGE_B;
        const size_t srcb = base + (size_t)k0 * 64;
        const int row = tid >> 3, ch = tid & 7;   // 512 threads = 64x8 chunks
        const uint32_t off = row * AP + ch * 16;
        const size_t g = srcb + (size_t)row * 64 + ch * 8;
        cp16(st + off, kh + g);
        cp16(st + KV_TILE_B + off, kl + g);
        cp16(st + 2 * KV_TILE_B + off, vh + g);
        cp16(st + 3 * KV_TILE_B + off, vl + g);
    };
    load_kv(0, 0);
    CP_COMMIT();

    CP_WAIT1();
    __syncthreads();

    uint32_t aqh[4][4], aql[4][4];
    #pragma unroll
    for (int kk = 0; kk < 4; kk++) {
        const uint32_t off = (warp * 16 + l_sub) * AP + (kk * 2 + l_cc) * 16;
        ldsm4(aqh[kk], sb + off);
        ldsm4(aql[kk], sb + Q2_BYTES + off);
    }

    float m0r = -1e30f, m1r = -1e30f, l0 = 0.f, l1 = 0.f;
    float o[8][4];
    #pragma unroll
    for (int j = 0; j < 8; j++)
        #pragma unroll
        for (int r = 0; r < 4; r++) o[j][r] = 0.f;

    const int r0g = q0 + warp * 16 + lq;
    const int r1g = r0g + 8;
    const int rowmaxw = q0 + warp * 16 + 15;

    for (int kt = 0; kt < nt; kt++) {
        const int k0 = kt * 64;
        if (kt + 1 < nt) load_kv((kt + 1) & 1, (kt + 1) * 64);
        CP_COMMIT();
        CP_WAIT1();
        __syncthreads();

        if (k0 <= rowmaxw) {
            const uint32_t st = sb + 2 * Q2_BYTES + (kt & 1) * KV_STAGE_B;

            float s[8][4];
            #pragma unroll
            for (int j = 0; j < 8; j++)
                #pragma unroll
                for (int r = 0; r < 4; r++) s[j][r] = 0.f;

            #pragma unroll
            for (int kk = 0; kk < 4; kk++) {
                uint32_t bk[8][2];
                #pragma unroll
                for (int j2 = 0; j2 < 4; j2++) {
                    uint32_t r[4];
                    ldsm4(r, st + (j2 * 16 + l_sub) * AP + (kk * 2 + l_cc) * 16);
                    bk[j2 * 2][0] = r[0];     bk[j2 * 2][1] = r[2];
                    bk[j2 * 2 + 1][0] = r[1]; bk[j2 * 2 + 1][1] = r[3];
                }
                #pragma unroll
                for (int j = 0; j < 8; j++) mma16816(s[j], aqh[kk], bk[j]);
                #pragma unroll
                for (int j = 0; j < 8; j++) mma16816(s[j], aql[kk], bk[j]);
                #pragma unroll
                for (int j2 = 0; j2 < 4; j2++) {
                    uint32_t r[4];
                    ldsm4(r, st + KV_TILE_B + (j2 * 16 + l_sub) * AP + (kk * 2 + l_cc) * 16);
                    bk[j2 * 2][0] = r[0];     bk[j2 * 2][1] = r[2];
                    bk[j2 * 2 + 1][0] = r[1]; bk[j2 * 2 + 1][1] = r[3];
                }
                #pragma unroll
                for (int j = 0; j < 8; j++) mma16816(s[j], aqh[kk], bk[j]);
            }

            if (k0 + 63 > q0 + warp * 16) {
                #pragma unroll
                for (int j = 0; j < 8; j++) {
                    const int c = k0 + 8 * j + 2 * lr;
                    if (c > r0g)     s[j][0] = -1e30f;
                    if (c + 1 > r0g) s[j][1] = -1e30f;
                    if (c > r1g)     s[j][2] = -1e30f;
                    if (c + 1 > r1g) s[j][3] = -1e30f;
                }
            }

            float mx0 = -1e30f, mx1 = -1e30f;
            #pragma unroll
            for (int j = 0; j < 8; j++) {
                mx0 = fmaxf(mx0, fmaxf(s[j][0], s[j][1]));
                mx1 = fmaxf(mx1, fmaxf(s[j][2], s[j][3]));
            }
            #pragma unroll
            for (int off = 1; off <= 2; off <<= 1) {
                mx0 = fmaxf(mx0, __shfl_xor_sync(0xffffffffu, mx0, off));
                mx1 = fmaxf(mx1, __shfl_xor_sync(0xffffffffu, mx1, off));
            }
            const float mn0 = fmaxf(m0r, mx0), mn1 = fmaxf(m1r, mx1);
            const float c0 = __expf(m0r - mn0), c1 = __expf(m1r - mn1);
            m0r = mn0; m1r = mn1;

            float rs0 = 0.f, rs1 = 0.f;
            #pragma unroll
            for (int j = 0; j < 8; j++) {
                s[j][0] = __expf(s[j][0] - mn0);
                s[j][1] = __expf(s[j][1] - mn0);
                s[j][2] = __expf(s[j][2] - mn1);
                s[j][3] = __expf(s[j][3] - mn1);
                rs0 += s[j][0] + s[j][1];
                rs1 += s[j][2] + s[j][3];
            }
            #pragma unroll
            for (int off = 1; off <= 2; off <<= 1) {
                rs0 += __shfl_xor_sync(0xffffffffu, rs0, off);
                rs1 += __shfl_xor_sync(0xffffffffu, rs1, off);
            }
            l0 = l0 * c0 + rs0;
            l1 = l1 * c1 + rs1;
            #pragma unroll
            for (int j = 0; j < 8; j++) {
                o[j][0] *= c0; o[j][1] *= c0;
                o[j][2] *= c1; o[j][3] *= c1;
            }

            #pragma unroll
            for (int kg = 0; kg < 4; kg++) {
                uint32_t ah[4], al[4];
                split_pack(s[2 * kg][0], s[2 * kg][1], ah[0], al[0]);
                split_pack(s[2 * kg][2], s[2 * kg][3], ah[1], al[1]);
                split_pack(s[2 * kg + 1][0], s[2 * kg + 1][1], ah[2], al[2]);
                split_pack(s[2 * kg + 1][2], s[2 * kg + 1][3], ah[3], al[3]);

                const int mm = lane >> 3;
                const int rowv = kg * 16 + (mm & 1) * 8 + (lane & 7);
                const int chb = mm >> 1;

                uint32_t bv[8][2];
                #pragma unroll
                for (int dg = 0; dg < 4; dg++) {
                    uint32_t r[4];
                    ldsm4t(r, st + 2 * KV_TILE_B + rowv * AP + (dg * 2 + chb) * 16);
                    bv[dg * 2][0] = r[0];     bv[dg * 2][1] = r[1];
                    bv[dg * 2 + 1][0] = r[2]; bv[dg * 2 + 1][1] = r[3];
                }
                #pragma unroll
                for (int jn = 0; jn < 8; jn++) mma16816(o[jn], ah, bv[jn]);
                #pragma unroll
                for (int jn = 0; jn < 8; jn++) mma16816(o[jn], al, bv[jn]);
                #pragma unroll
                for (int dg = 0; dg < 4; dg++) {
                    uint32_t r[4];
                    ldsm4t(r, st + 3 * KV_TILE_B + rowv * AP + (dg * 2 + chb) * 16);
                    bv[dg * 2][0] = r[0];     bv[dg * 2][1] = r[1];
                    bv[dg * 2 + 1][0] = r[2]; bv[dg * 2 + 1][1] = r[3];
                }
                #pragma unroll
                for (int jn = 0; jn < 8; jn++) mma16816(o[jn], ah, bv[jn]);
            }
        }
        __syncthreads();
    }

    const float inv0 = 1.0f / l0;
    const float inv1 = 1.0f / l1;
    const size_t tok0 = (size_t)(b * TT + q0 + warp * 16 + lq);
    const size_t tok1 = tok0 + 8;
    #pragma unroll
    for (int jn = 0; jn < 8; jn++) {
        const int d = 8 * jn + 2 * lr;
        uint32_t hp, lp;
        split_pack(o[jn][0] * inv0, o[jn][1] * inv0, hp, lp);
        const size_t off0 = (tok0 * DD + h * 64 + d) >> 1;
        ((uint32_t*)yh)[off0] = hp; ((uint32_t*)yl)[off0] = lp;
        split_pack(o[jn][2] * inv1, o[jn][3] * inv1, hp, lp);
        const size_t off1 = (tok1 * DD + h * 64 + d) >> 1;
        ((uint32_t*)yh)[off1] = hp; ((uint32_t*)yl)[off1] = lp;
    }
}

// ---------------------------------------------------------------------------
// Host side
// ---------------------------------------------------------------------------
extern "C" void kernel_launch(void* const* d_in, const int* in_sizes, int n_in,
                              void* d_out, int out_size) {
    const float* x      = (const float*)d_in[0];
    const float* w_qkv  = (const float*)d_in[2];
    const float* b_qkv  = (const float*)d_in[3];
    const float* w_proj = (const float*)d_in[4];
    const float* b_proj = (const float*)d_in[5];
    float* out = (float*)d_out;

    void *pxh, *pxl, *pwqh, *pwql, *pwph, *pwpl, *pyh, *pyl;
    void *pqh, *pql, *pkh, *pkl, *pvh, *pvl;
    cudaGetSymbolAddress(&pxh, g_xh);   cudaGetSymbolAddress(&pxl, g_xl);
    cudaGetSymbolAddress(&pwqh, g_wqh); cudaGetSymbolAddress(&pwql, g_wql);
    cudaGetSymbolAddress(&pwph, g_wph); cudaGetSymbolAddress(&pwpl, g_wpl);
    cudaGetSymbolAddress(&pyh, g_yh);   cudaGetSymbolAddress(&pyl, g_yl);
    cudaGetSymbolAddress(&pqh, g_qh);   cudaGetSymbolAddress(&pql, g_ql);
    cudaGetSymbolAddress(&pkh, g_kh);   cudaGetSymbolAddress(&pkl, g_kl);
    cudaGetSymbolAddress(&pvh, g_vh);   cudaGetSymbolAddress(&pvl, g_vl);

    static int attr_set = 0;
    if (!attr_set) {
        cudaFuncSetAttribute(qkv_gemm_kernel,
                             cudaFuncAttributeMaxDynamicSharedMemorySize, 4 * STAGE4_B);
        cudaFuncSetAttribute(proj_gemm_kernel,
                             cudaFuncAttributeMaxDynamicSharedMemorySize, 4 * STAGE4_B);
        cudaFuncSetAttribute(attn_mma_kernel,
                             cudaFuncAttributeMaxDynamicSharedMemorySize, ATT_SMEM);
        attr_set = 1;
    }

    // 1) split inputs to bf16 hi/lo
    split_kernel<<<(MROWS * DD) / 1024, 256>>>(x, (__nv_bfloat16*)pxh, (__nv_bfloat16*)pxl,
                                               (MROWS * DD) / 4);
    split_kernel<<<(3 * DD * DD) / 1024, 256>>>(w_qkv, (__nv_bfloat16*)pwqh, (__nv_bfloat16*)pwql,
                                                (3 * DD * DD) / 4);
    split_kernel<<<(DD * DD) / 1024, 256>>>(w_proj, (__nv_bfloat16*)pwph, (__nv_bfloat16*)pwpl,
                                            (DD * DD) / 4);

    // 2) QKV GEMM -> q/k/v hi/lo in [b,h,t,d] (q pre-scaled by 1/8)
    {
        dim3 grid((3 * DD) / 128, MROWS / 128);
        qkv_gemm_kernel<<<grid, 256, 4 * STAGE4_B>>>(
            (const __nv_bfloat16*)pxh, (const __nv_bfloat16*)pxl,
            (const __nv_bfloat16*)pwqh, (const __nv_bfloat16*)pwql,
            b_qkv,
            (__nv_bfloat16*)pqh, (__nv_bfloat16*)pql,
            (__nv_bfloat16*)pkh, (__nv_bfloat16*)pkl,
            (__nv_bfloat16*)pvh, (__nv_bfloat16*)pvl);
    }

    // 3) flash attention (mma.sync, 512 threads / 256 q rows) -> y hi/lo
    {
        dim3 grid(TT / 256, HH, BB);
        attn_mma_kernel<<<grid, 512, ATT_SMEM>>>(
            (const __nv_bfloat16*)pqh, (const __nv_bfloat16*)pql,
            (const __nv_bfloat16*)pkh, (const __nv_bfloat16*)pkl,
            (const __nv_bfloat16*)pvh, (const __nv_bfloat16*)pvl,
            (__nv_bfloat16*)pyh, (__nv_bfloat16*)pyl);
    }

    // 4) output projection -> out (fp32)
    {
        dim3 grid(DD / 128, MROWS / 128);
        proj_gemm_kernel<<<grid, 256, 4 * STAGE4_B>>>(
            (const __nv_bfloat16*)pyh, (const __nv_bfloat16*)pyl,
            (const __nv_bfloat16*)pwph, (const __nv_bfloat16*)pwpl,
            b_proj, out, DD);
    }
}

// round 11
// speedup vs baseline: 1.1486x; 1.1486x over previous
#include <cuda_runtime.h>
#include <cuda_bf16.h>
#include <cstdint>
#include <math.h>

#define BB 2
#define TT 2048
#define DD 1024
#define HH 16
#define HDIM 64
#define MROWS (BB * TT)   // 4096

// ---------------------------------------------------------------------------
// Scratch (device globals; no allocation anywhere)
// ---------------------------------------------------------------------------
__device__ __align__(256) __nv_bfloat16 g_xh[(size_t)MROWS * DD];
__device__ __align__(256) __nv_bfloat16 g_xl[(size_t)MROWS * DD];
__device__ __align__(256) __nv_bfloat16 g_wqh[(size_t)3 * DD * DD];
__device__ __align__(256) __nv_bfloat16 g_wql[(size_t)3 * DD * DD];
__device__ __align__(256) __nv_bfloat16 g_wph[(size_t)DD * DD];
__device__ __align__(256) __nv_bfloat16 g_wpl[(size_t)DD * DD];
__device__ __align__(256) __nv_bfloat16 g_yh[(size_t)MROWS * DD];
__device__ __align__(256) __nv_bfloat16 g_yl[(size_t)MROWS * DD];
// q/k/v in [b,h,t,d] layout, hi/lo bf16
__device__ __align__(256) __nv_bfloat16 g_qh[(size_t)MROWS * DD];
__device__ __align__(256) __nv_bfloat16 g_ql[(size_t)MROWS * DD];
__device__ __align__(256) __nv_bfloat16 g_kh[(size_t)MROWS * DD];
__device__ __align__(256) __nv_bfloat16 g_kl[(size_t)MROWS * DD];
__device__ __align__(256) __nv_bfloat16 g_vh[(size_t)MROWS * DD];
__device__ __align__(256) __nv_bfloat16 g_vl[(size_t)MROWS * DD];

// ---------------------------------------------------------------------------
// helpers
// ---------------------------------------------------------------------------
__device__ __forceinline__ uint32_t smem_u32(const void* p) {
    uint32_t a;
    asm("{ .reg .u64 t; cvta.to.shared.u64 t, %1; cvt.u32.u64 %0, t; }"
        : "=r"(a) : "l"(p));
    return a;
}
__device__ __forceinline__ void cp16(uint32_t d, const void* g) {
    asm volatile("cp.async.cg.shared.global [%0], [%1], 16;" :: "r"(d), "l"(g));
}
__device__ __forceinline__ void ldsm4(uint32_t* r, uint32_t a) {
    asm volatile("ldmatrix.sync.aligned.m8n8.x4.shared.b16 {%0,%1,%2,%3}, [%4];"
        : "=r"(r[0]), "=r"(r[1]), "=r"(r[2]), "=r"(r[3]) : "r"(a));
}
__device__ __forceinline__ void ldsm4t(uint32_t* r, uint32_t a) {
    asm volatile("ldmatrix.sync.aligned.m8n8.x4.trans.shared.b16 {%0,%1,%2,%3}, [%4];"
        : "=r"(r[0]), "=r"(r[1]), "=r"(r[2]), "=r"(r[3]) : "r"(a));
}
__device__ __forceinline__ void mma16816(float* c, const uint32_t* a, const uint32_t* b) {
    asm volatile("mma.sync.aligned.m16n8k16.row.col.f32.bf16.bf16.f32 "
        "{%0,%1,%2,%3}, {%4,%5,%6,%7}, {%8,%9}, {%0,%1,%2,%3};"
        : "+f"(c[0]), "+f"(c[1]), "+f"(c[2]), "+f"(c[3])
        : "r"(a[0]), "r"(a[1]), "r"(a[2]), "r"(a[3]), "r"(b[0]), "r"(b[1]));
}
__device__ __forceinline__ uint32_t bfpack(float lo, float hi) {
    uint32_t r;
    asm("cvt.rn.bf16x2.f32 %0, %1, %2;" : "=r"(r) : "f"(hi), "f"(lo));
    return r;
}
__device__ __forceinline__ void split_pack(float v0, float v1, uint32_t& hp, uint32_t& lp) {
    __nv_bfloat16 h0 = __float2bfloat16(v0), h1 = __float2bfloat16(v1);
    hp = ((uint32_t)__bfloat16_as_ushort(h1) << 16) | (uint32_t)__bfloat16_as_ushort(h0);
    lp = bfpack(v0 - __bfloat162float(h0), v1 - __bfloat162float(h1));
}
#define CP_COMMIT() asm volatile("cp.async.commit_group;" ::: "memory")
#define CP_WAIT1()  asm volatile("cp.async.wait_group 1;" ::: "memory")

// ---------------------------------------------------------------------------
// fp32 -> bf16 hi/lo split (inputs)
// ---------------------------------------------------------------------------
__global__ __launch_bounds__(256) void split_kernel(const float* __restrict__ in,
                                                    __nv_bfloat16* __restrict__ hi,
                                                    __nv_bfloat16* __restrict__ lo,
                                                    int n4) {
    int i = blockIdx.x * blockDim.x + threadIdx.x;
    if (i >= n4) return;
    float4 v = ((const float4*)in)[i];
    uint32_t h0, l0, h1, l1;
    split_pack(v.x, v.y, h0, l0);
    split_pack(v.z, v.w, h1, l1);
    ((uint32_t*)hi)[2 * i] = h0; ((uint32_t*)hi)[2 * i + 1] = h1;
    ((uint32_t*)lo)[2 * i] = l0; ((uint32_t*)lo)[2 * i + 1] = l1;
}

// ---------------------------------------------------------------------------
// Fused 3-term bf16x3 GEMM: C = Ah*(Bh+Bl) + Al*Bh (+bias)
// Stage = {Ah, Al, Bh, Bl} 128x32 tiles, 80B pitch, 40KB/stage, GS=2.
// b-fragments processed in two j-halves to bound regs (<=128, 2 CTA/SM).
// Term-major MMA ordering within each half: RAW reuse distance 8.
// ---------------------------------------------------------------------------
#define TILE_B 10240            // 128 rows * 80B
#define STAGE4_B (4 * TILE_B)   // Ah, Al, Bh, Bl
#define NIT 32

__device__ __forceinline__ void load_stage4(uint32_t st,
                                            const __nv_bfloat16* __restrict__ Ah,
                                            const __nv_bfloat16* __restrict__ Al,
                                            const __nv_bfloat16* __restrict__ Bh,
                                            const __nv_bfloat16* __restrict__ Bl,
                                            int m0, int n0, int kk, int tid) {
    #pragma unroll
    for (int t = 0; t < 2; t++) {
        const int chunk = tid + t * 256;        // 0..511
        const int row = chunk >> 2;             // 0..127
        const int cc  = chunk & 3;
        const uint32_t off = row * 80 + cc * 16;
        const size_t ga = (size_t)(m0 + row) * DD + kk + cc * 8;
        const size_t gb = (size_t)(n0 + row) * DD + kk + cc * 8;
        cp16(st + off,              Ah + ga);
        cp16(st + TILE_B + off,     Al + ga);
        cp16(st + 2 * TILE_B + off, Bh + gb);
        cp16(st + 3 * TILE_B + off, Bl + gb);
    }
}

__device__ __forceinline__ void gemm_mainloop(uint32_t sbase,
                                              const __nv_bfloat16* __restrict__ Ah,
                                              const __nv_bfloat16* __restrict__ Al,
                                              const __nv_bfloat16* __restrict__ Bh,
                                              const __nv_bfloat16* __restrict__ Bl,
                                              int m0, int n0, int tid,
                                              float (&acc)[2][8][4]) {
    const int lane = tid & 31;
    const int warp = tid >> 5;
    const int wm = warp >> 1;
    const int wn = warp & 1;

    // prologue: two stages in flight
    load_stage4(sbase, Ah, Al, Bh, Bl, m0, n0, 0, tid);
    CP_COMMIT();
    load_stage4(sbase + STAGE4_B, Ah, Al, Bh, Bl, m0, n0, 32, tid);
    CP_COMMIT();

    const int l_sub = lane & 15;
    const int l_cc  = lane >> 4;

    for (int it = 0; it < NIT; it++) {
        const uint32_t st = sbase + (it & 1) * STAGE4_B;
        CP_WAIT1();             // current stage landed (next may still fly)
        __syncthreads();

        #pragma unroll
        for (int h = 0; h < 2; h++) {
            const int cc = h * 2 + l_cc;
            uint32_t ah[2][4], al[2][4];
            #pragma unroll
            for (int i = 0; i < 2; i++) {
                const uint32_t ro = (wm * 32 + i * 16 + l_sub) * 80 + cc * 16;
                ldsm4(ah[i], st + ro);
                ldsm4(al[i], st + TILE_B + ro);
            }
            #pragma unroll
            for (int jh = 0; jh < 2; jh++) {
                uint32_t bh[4][2], bl[4][2];
                #pragma unroll
                for (int j2 = 0; j2 < 2; j2++) {
                    const uint32_t ro = (wn * 64 + jh * 32 + j2 * 16 + l_sub) * 80 + cc * 16;
                    uint32_t r[4];
                    ldsm4(r, st + 2 * TILE_B + ro);
                    bh[j2 * 2][0] = r[0];     bh[j2 * 2][1] = r[2];
                    bh[j2 * 2 + 1][0] = r[1]; bh[j2 * 2 + 1][1] = r[3];
                    ldsm4(r, st + 3 * TILE_B + ro);
                    bl[j2 * 2][0] = r[0];     bl[j2 * 2][1] = r[2];
                    bl[j2 * 2 + 1][0] = r[1]; bl[j2 * 2 + 1][1] = r[3];
                }
                // term-major: 8 independent accumulators between RAW reuse
                #pragma unroll
                for (int i = 0; i < 2; i++)
                    #pragma unroll
                    for (int j = 0; j < 4; j++) mma16816(acc[i][jh * 4 + j], ah[i], bh[j]);
                #pragma unroll
                for (int i = 0; i < 2; i++)
                    #pragma unroll
                    for (int j = 0; j < 4; j++) mma16816(acc[i][jh * 4 + j], ah[i], bl[j]);
                #pragma unroll
                for (int i = 0; i < 2; i++)
                    #pragma unroll
                    for (int j = 0; j < 4; j++) mma16816(acc[i][jh * 4 + j], al[i], bh[j]);
            }
        }

        __syncthreads();        // stage fully consumed before refill
        if (it + 2 < NIT) {
            load_stage4(st, Ah, Al, Bh, Bl, m0, n0, (it + 2) << 5, tid);
        }
        CP_COMMIT();
    }
}

// ---- qkv GEMM: scatter epilogue -> q/k/v hi/lo in [b,h,t,d] (q scaled) ----
__global__ __launch_bounds__(256, 2)
void qkv_gemm_kernel(const __nv_bfloat16* __restrict__ Ah,
                     const __nv_bfloat16* __restrict__ Al,
                     const __nv_bfloat16* __restrict__ Bh,
                     const __nv_bfloat16* __restrict__ Bl,
                     const float* __restrict__ bias,
                     __nv_bfloat16* __restrict__ qh, __nv_bfloat16* __restrict__ ql,
                     __nv_bfloat16* __restrict__ kh, __nv_bfloat16* __restrict__ kl,
                     __nv_bfloat16* __restrict__ vh, __nv_bfloat16* __restrict__ vl) {
    extern __shared__ __align__(1024) char sm[];
    const uint32_t sbase = smem_u32(sm);
    const int tid = threadIdx.x;
    const int lane = tid & 31;
    const int warp = tid >> 5;
    const int wm = warp >> 1, wn = warp & 1;
    const int m0 = blockIdx.y * 128;
    const int n0 = blockIdx.x * 128;

    float acc[2][8][4];
    #pragma unroll
    for (int i = 0; i < 2; i++)
        #pragma unroll
        for (int j = 0; j < 8; j++)
            #pragma unroll
            for (int r = 0; r < 4; r++) acc[i][j][r] = 0.f;

    gemm_mainloop(sbase, Ah, Al, Bh, Bl, m0, n0, tid, acc);

    const int l4 = lane >> 2;
    const int l2 = (lane & 3) << 1;
    #pragma unroll
    for (int i = 0; i < 2; i++) {
        const int row = m0 + wm * 32 + i * 16 + l4;   // token index
        const int bi = row >> 11;
        const int t  = row & 2047;
        #pragma unroll
        for (int j = 0; j < 8; j++) {
            const int col = n0 + wn * 64 + j * 8 + l2;
            const int type = col >> 10;
            const int hc = (col & 1023) >> 6;
            const int d  = col & 63;
            const float2 bv = *(const float2*)(bias + col);
            float v0 = acc[i][j][0] + bv.x, v1 = acc[i][j][1] + bv.y;
            float v2 = acc[i][j][2] + bv.x, v3 = acc[i][j][3] + bv.y;
            if (type == 0) { v0 *= 0.125f; v1 *= 0.125f; v2 *= 0.125f; v3 *= 0.125f; }
            __nv_bfloat16* dh = (type == 0) ? qh : (type == 1) ? kh : vh;
            __nv_bfloat16* dl = (type == 0) ? ql : (type == 1) ? kl : vl;
            const size_t off0 = (((size_t)(bi * HH + hc)) * TT + t) * 64 + d;
            const size_t off1 = off0 + 8 * 64;
            uint32_t hp, lp;
            split_pack(v0, v1, hp, lp);
            ((uint32_t*)dh)[off0 >> 1] = hp; ((uint32_t*)dl)[off0 >> 1] = lp;
            split_pack(v2, v3, hp, lp);
            ((uint32_t*)dh)[off1 >> 1] = hp; ((uint32_t*)dl)[off1 >> 1] = lp;
        }
    }
}

// ---- proj GEMM: fp32 epilogue ----
__global__ __launch_bounds__(256, 2)
void proj_gemm_kernel(const __nv_bfloat16* __restrict__ Ah,
                      const __nv_bfloat16* __restrict__ Al,
                      const __nv_bfloat16* __restrict__ Bh,
                      const __nv_bfloat16* __restrict__ Bl,
                      const float* __restrict__ bias,
                      float* __restrict__ C, int ldc) {
    extern __shared__ __align__(1024) char sm[];
    const uint32_t sbase = smem_u32(sm);
    const int tid = threadIdx.x;
    const int lane = tid & 31;
    const int warp = tid >> 5;
    const int wm = warp >> 1, wn = warp & 1;
    const int m0 = blockIdx.y * 128;
    const int n0 = blockIdx.x * 128;

    float acc[2][8][4];
    #pragma unroll
    for (int i = 0; i < 2; i++)
        #pragma unroll
        for (int j = 0; j < 8; j++)
            #pragma unroll
            for (int r = 0; r < 4; r++) acc[i][j][r] = 0.f;

    gemm_mainloop(sbase, Ah, Al, Bh, Bl, m0, n0, tid, acc);

    const int l4 = lane >> 2;
    const int l2 = (lane & 3) << 1;
    #pragma unroll
    for (int i = 0; i < 2; i++) {
        const int row0 = m0 + wm * 32 + i * 16 + l4;
        #pragma unroll
        for (int j = 0; j < 8; j++) {
            const int col = n0 + wn * 64 + j * 8 + l2;
            const float2 bv = *(const float2*)(bias + col);
            float2 v0, v1;
            v0.x = acc[i][j][0] + bv.x; v0.y = acc[i][j][1] + bv.y;
            v1.x = acc[i][j][2] + bv.x; v1.y = acc[i][j][3] + bv.y;
            *(float2*)(C + (size_t)row0 * ldc + col) = v0;
            *(float2*)(C + (size_t)(row0 + 8) * ldc + col) = v1;
        }
    }
}

// ---------------------------------------------------------------------------
// Flash attention on mma.sync (bf16x3) -- R7-validated version (256 threads,
// 128 q rows/CTA, kv tiles of 64 double-buffered)
// ---------------------------------------------------------------------------
#define AP 144
#define Q_BYTES (128 * AP)
#define KV_TILE_B (64 * AP)
#define KV_STAGE_B (4 * KV_TILE_B)
#define ATT_SMEM (2 * Q_BYTES + 2 * KV_STAGE_B)

__global__ __launch_bounds__(256, 1)
void attn_mma_kernel(const __nv_bfloat16* __restrict__ qh, const __nv_bfloat16* __restrict__ ql,
                     const __nv_bfloat16* __restrict__ kh, const __nv_bfloat16* __restrict__ kl,
                     const __nv_bfloat16* __restrict__ vh, const __nv_bfloat16* __restrict__ vl,
                     __nv_bfloat16* __restrict__ yh, __nv_bfloat16* __restrict__ yl) {
    extern __shared__ __align__(1024) char sm[];
    const uint32_t sb = smem_u32(sm);

    const int qi = blockIdx.x;
    const int h  = blockIdx.y;
    const int b  = blockIdx.z;
    const int q0 = qi * 128;
    const size_t base = ((size_t)(b * HH + h)) * TT * 64;

    const int tid  = threadIdx.x;
    const int warp = tid >> 5;
    const int lane = tid & 31;
    const int l_sub = lane & 15;
    const int l_cc  = lane >> 4;
    const int lq = lane >> 2;
    const int lr = lane & 3;

    #pragma unroll
    for (int t2 = 0; t2 < 4; t2++) {
        const int idx = tid + t2 * 256;
        const int row = idx >> 3, ch = idx & 7;
        const uint32_t off = row * AP + ch * 16;
        const size_t g = base + (size_t)(q0 + row) * 64 + ch * 8;
        cp16(sb + off, qh + g);
        cp16(sb + Q_BYTES + off, ql + g);
    }
    CP_COMMIT();

    const int nt = 2 * qi + 2;
    auto load_kv = [&](int s, int k0) {
        const uint32_t st = sb + 2 * Q_BYTES + s * KV_STAGE_B;
        const size_t srcb = base + (size_t)k0 * 64;
        #pragma unroll
        for (int t2 = 0; t2 < 2; t2++) {
            const int idx = tid + t2 * 256;
            const int row = idx >> 3, ch = idx & 7;
            const uint32_t off = row * AP + ch * 16;
            const size_t g = srcb + (size_t)row * 64 + ch * 8;
            cp16(st + off, kh + g);
            cp16(st + KV_TILE_B + off, kl + g);
            cp16(st + 2 * KV_TILE_B + off, vh + g);
            cp16(st + 3 * KV_TILE_B + off, vl + g);
        }
    };
    load_kv(0, 0);
    CP_COMMIT();

    CP_WAIT1();
    __syncthreads();

    uint32_t aqh[4][4], aql[4][4];
    #pragma unroll
    for (int kk = 0; kk < 4; kk++) {
        const uint32_t off = (warp * 16 + l_sub) * AP + (kk * 2 + l_cc) * 16;
        ldsm4(aqh[kk], sb + off);
        ldsm4(aql[kk], sb + Q_BYTES + off);
    }

    float m0r = -1e30f, m1r = -1e30f, l0 = 0.f, l1 = 0.f;
    float o[8][4];
    #pragma unroll
    for (int j = 0; j < 8; j++)
        #pragma unroll
        for (int r = 0; r < 4; r++) o[j][r] = 0.f;

    const int r0g = q0 + warp * 16 + lq;
    const int r1g = r0g + 8;
    const int rowmaxw = q0 + warp * 16 + 15;

    for (int kt = 0; kt < nt; kt++) {
        const int k0 = kt * 64;
        if (kt + 1 < nt) load_kv((kt + 1) & 1, (kt + 1) * 64);
        CP_COMMIT();
        CP_WAIT1();
        __syncthreads();

        if (k0 <= rowmaxw) {
            const uint32_t st = sb + 2 * Q_BYTES + (kt & 1) * KV_STAGE_B;

            float s[8][4];
            #pragma unroll
            for (int j = 0; j < 8; j++)
                #pragma unroll
                for (int r = 0; r < 4; r++) s[j][r] = 0.f;

            #pragma unroll
            for (int kk = 0; kk < 4; kk++) {
                uint32_t bk[8][2];
                #pragma unroll
                for (int j2 = 0; j2 < 4; j2++) {
                    uint32_t r[4];
                    ldsm4(r, st + (j2 * 16 + l_sub) * AP + (kk * 2 + l_cc) * 16);
                    bk[j2 * 2][0] = r[0];     bk[j2 * 2][1] = r[2];
                    bk[j2 * 2 + 1][0] = r[1]; bk[j2 * 2 + 1][1] = r[3];
                }
                #pragma unroll
                for (int j = 0; j < 8; j++) mma16816(s[j], aqh[kk], bk[j]);
                #pragma unroll
                for (int j = 0; j < 8; j++) mma16816(s[j], aql[kk], bk[j]);
                #pragma unroll
                for (int j2 = 0; j2 < 4; j2++) {
                    uint32_t r[4];
                    ldsm4(r, st + KV_TILE_B + (j2 * 16 + l_sub) * AP + (kk * 2 + l_cc) * 16);
                    bk[j2 * 2][0] = r[0];     bk[j2 * 2][1] = r[2];
                    bk[j2 * 2 + 1][0] = r[1]; bk[j2 * 2 + 1][1] = r[3];
                }
                #pragma unroll
                for (int j = 0; j < 8; j++) mma16816(s[j], aqh[kk], bk[j]);
            }

            if (k0 + 63 > q0 + warp * 16) {
                #pragma unroll
                for (int j = 0; j < 8; j++) {
                    const int c = k0 + 8 * j + 2 * lr;
                    if (c > r0g)     s[j][0] = -1e30f;
                    if (c + 1 > r0g) s[j][1] = -1e30f;
                    if (c > r1g)     s[j][2] = -1e30f;
                    if (c + 1 > r1g) s[j][3] = -1e30f;
                }
            }

            float mx0 = -1e30f, mx1 = -1e30f;
            #pragma unroll
            for (int j = 0; j < 8; j++) {
                mx0 = fmaxf(mx0, fmaxf(s[j][0], s[j][1]));
                mx1 = fmaxf(mx1, fmaxf(s[j][2], s[j][3]));
            }
            #pragma unroll
            for (int off = 1; off <= 2; off <<= 1) {
                mx0 = fmaxf(mx0, __shfl_xor_sync(0xffffffffu, mx0, off));
                mx1 = fmaxf(mx1, __shfl_xor_sync(0xffffffffu, mx1, off));
            }
            const float mn0 = fmaxf(m0r, mx0), mn1 = fmaxf(m1r, mx1);
            const float c0 = __expf(m0r - mn0), c1 = __expf(m1r - mn1);
            m0r = mn0; m1r = mn1;

            float rs0 = 0.f, rs1 = 0.f;
            #pragma unroll
            for (int j = 0; j < 8; j++) {
                s[j][0] = __expf(s[j][0] - mn0);
                s[j][1] = __expf(s[j][1] - mn0);
                s[j][2] = __expf(s[j][2] - mn1);
                s[j][3] = __expf(s[j][3] - mn1);
                rs0 += s[j][0] + s[j][1];
                rs1 += s[j][2] + s[j][3];
            }
            #pragma unroll
            for (int off = 1; off <= 2; off <<= 1) {
                rs0 += __shfl_xor_sync(0xffffffffu, rs0, off);
                rs1 += __shfl_xor_sync(0xffffffffu, rs1, off);
            }
            l0 = l0 * c0 + rs0;
            l1 = l1 * c1 + rs1;
            #pragma unroll
            for (int j = 0; j < 8; j++) {
                o[j][0] *= c0; o[j][1] *= c0;
                o[j][2] *= c1; o[j][3] *= c1;
            }

            #pragma unroll
            for (int kg = 0; kg < 4; kg++) {
                uint32_t ah[4], al[4];
                split_pack(s[2 * kg][0], s[2 * kg][1], ah[0], al[0]);
                split_pack(s[2 * kg][2], s[2 * kg][3], ah[1], al[1]);
                split_pack(s[2 * kg + 1][0], s[2 * kg + 1][1], ah[2], al[2]);
                split_pack(s[2 * kg + 1][2], s[2 * kg + 1][3], ah[3], al[3]);

                const int mm = lane >> 3;
                const int rowv = kg * 16 + (mm & 1) * 8 + (lane & 7);
                const int chb = mm >> 1;

                uint32_t bv[8][2];
                #pragma unroll
                for (int dg = 0; dg < 4; dg++) {
                    uint32_t r[4];
                    ldsm4t(r, st + 2 * KV_TILE_B + rowv * AP + (dg * 2 + chb) * 16);
                    bv[dg * 2][0] = r[0];     bv[dg * 2][1] = r[1];
                    bv[dg * 2 + 1][0] = r[2]; bv[dg * 2 + 1][1] = r[3];
                }
                #pragma unroll
                for (int jn = 0; jn < 8; jn++) mma16816(o[jn], ah, bv[jn]);
                #pragma unroll
                for (int jn = 0; jn < 8; jn++) mma16816(o[jn], al, bv[jn]);
                #pragma unroll
                for (int dg = 0; dg < 4; dg++) {
                    uint32_t r[4];
                    ldsm4t(r, st + 3 * KV_TILE_B + rowv * AP + (dg * 2 + chb) * 16);
                    bv[dg * 2][0] = r[0];     bv[dg * 2][1] = r[1];
                    bv[dg * 2 + 1][0] = r[2]; bv[dg * 2 + 1][1] = r[3];
                }
                #pragma unroll
                for (int jn = 0; jn < 8; jn++) mma16816(o[jn], ah, bv[jn]);
            }
        }
        __syncthreads();
    }

    const float inv0 = 1.0f / l0;
    const float inv1 = 1.0f / l1;
    const size_t tok0 = (size_t)(b * TT + q0 + warp * 16 + lq);
    const size_t tok1 = tok0 + 8;
    #pragma unroll
    for (int jn = 0; jn < 8; jn++) {
        const int d = 8 * jn + 2 * lr;
        uint32_t hp, lp;
        split_pack(o[jn][0] * inv0, o[jn][1] * inv0, hp, lp);
        const size_t off0 = (tok0 * DD + h * 64 + d) >> 1;
        ((uint32_t*)yh)[off0] = hp; ((uint32_t*)yl)[off0] = lp;
        split_pack(o[jn][2] * inv1, o[jn][3] * inv1, hp, lp);
        const size_t off1 = (tok1 * DD + h * 64 + d) >> 1;
        ((uint32_t*)yh)[off1] = hp; ((uint32_t*)yl)[off1] = lp;
    }
}

// ---------------------------------------------------------------------------
// Host side
// ---------------------------------------------------------------------------
extern "C" void kernel_launch(void* const* d_in, const int* in_sizes, int n_in,
                              void* d_out, int out_size) {
    const float* x      = (const float*)d_in[0];
    const float* w_qkv  = (const float*)d_in[2];
    const float* b_qkv  = (const float*)d_in[3];
    const float* w_proj = (const float*)d_in[4];
    const float* b_proj = (const float*)d_in[5];
    float* out = (float*)d_out;

    void *pxh, *pxl, *pwqh, *pwql, *pwph, *pwpl, *pyh, *pyl;
    void *pqh, *pql, *pkh, *pkl, *pvh, *pvl;
    cudaGetSymbolAddress(&pxh, g_xh);   cudaGetSymbolAddress(&pxl, g_xl);
    cudaGetSymbolAddress(&pwqh, g_wqh); cudaGetSymbolAddress(&pwql, g_wql);
    cudaGetSymbolAddress(&pwph, g_wph); cudaGetSymbolAddress(&pwpl, g_wpl);
    cudaGetSymbolAddress(&pyh, g_yh);   cudaGetSymbolAddress(&pyl, g_yl);
    cudaGetSymbolAddress(&pqh, g_qh);   cudaGetSymbolAddress(&pql, g_ql);
    cudaGetSymbolAddress(&pkh, g_kh);   cudaGetSymbolAddress(&pkl, g_kl);
    cudaGetSymbolAddress(&pvh, g_vh);   cudaGetSymbolAddress(&pvl, g_vl);

    static int attr_set = 0;
    if (!attr_set) {
        cudaFuncSetAttribute(qkv_gemm_kernel,
                             cudaFuncAttributeMaxDynamicSharedMemorySize, 2 * STAGE4_B);
        cudaFuncSetAttribute(proj_gemm_kernel,
                             cudaFuncAttributeMaxDynamicSharedMemorySize, 2 * STAGE4_B);
        cudaFuncSetAttribute(attn_mma_kernel,
                             cudaFuncAttributeMaxDynamicSharedMemorySize, ATT_SMEM);
        attr_set = 1;
    }

    // 1) split inputs to bf16 hi/lo
    split_kernel<<<(MROWS * DD) / 1024, 256>>>(x, (__nv_bfloat16*)pxh, (__nv_bfloat16*)pxl,
                                               (MROWS * DD) / 4);
    split_kernel<<<(3 * DD * DD) / 1024, 256>>>(w_qkv, (__nv_bfloat16*)pwqh, (__nv_bfloat16*)pwql,
                                                (3 * DD * DD) / 4);
    split_kernel<<<(DD * DD) / 1024, 256>>>(w_proj, (__nv_bfloat16*)pwph, (__nv_bfloat16*)pwpl,
                                            (DD * DD) / 4);

    // 2) QKV GEMM -> q/k/v hi/lo in [b,h,t,d] (q pre-scaled by 1/8)
    {
        dim3 grid((3 * DD) / 128, MROWS / 128);
        qkv_gemm_kernel<<<grid, 256, 2 * STAGE4_B>>>(
            (const __nv_bfloat16*)pxh, (const __nv_bfloat16*)pxl,
            (const __nv_bfloat16*)pwqh, (const __nv_bfloat16*)pwql,
            b_qkv,
            (__nv_bfloat16*)pqh, (__nv_bfloat16*)pql,
            (__nv_bfloat16*)pkh, (__nv_bfloat16*)pkl,
            (__nv_bfloat16*)pvh, (__nv_bfloat16*)pvl);
    }

    // 3) flash attention (mma.sync) -> y hi/lo
    {
        dim3 grid(TT / 128, HH, BB);
        attn_mma_kernel<<<grid, 256, ATT_SMEM>>>(
            (const __nv_bfloat16*)pqh, (const __nv_bfloat16*)pql,
            (const __nv_bfloat16*)pkh, (const __nv_bfloat16*)pkl,
            (const __nv_bfloat16*)pvh, (const __nv_bfloat16*)pvl,
            (__nv_bfloat16*)pyh, (__nv_bfloat16*)pyl);
    }

    // 4) output projection -> out (fp32)
    {
        dim3 grid(DD / 128, MROWS / 128);
        proj_gemm_kernel<<<grid, 256, 2 * STAGE4_B>>>(
            (const __nv_bfloat16*)pyh, (const __nv_bfloat16*)pyl,
            (const __nv_bfloat16*)pwph, (const __nv_bfloat16*)pwpl,
            b_proj, out, DD);
    }
}

// round 12
// speedup vs baseline: 2.7048x; 2.3550x over previous
#include <cuda_runtime.h>
#include <cuda_fp16.h>
#include <cstdint>
#include <math.h>

#define BB 2
#define TT 2048
#define DD 1024
#define HH 16
#define HDIM 64
#define MROWS (BB * TT)   // 4096

// ---------------------------------------------------------------------------
// Scratch (device globals; no allocation anywhere). All fp16 single-pass.
// ---------------------------------------------------------------------------
__device__ __align__(256) __half g_x16[(size_t)MROWS * DD];
__device__ __align__(256) __half g_wq16[(size_t)3 * DD * DD];
__device__ __align__(256) __half g_wp16[(size_t)DD * DD];
__device__ __align__(256) __half g_y16[(size_t)MROWS * DD];
// q/k/v in [b,h,t,d] layout
__device__ __align__(256) __half g_q16[(size_t)MROWS * DD];
__device__ __align__(256) __half g_k16[(size_t)MROWS * DD];
__device__ __align__(256) __half g_v16[(size_t)MROWS * DD];

// ---------------------------------------------------------------------------
// helpers
// ---------------------------------------------------------------------------
__device__ __forceinline__ uint32_t smem_u32(const void* p) {
    uint32_t a;
    asm("{ .reg .u64 t; cvta.to.shared.u64 t, %1; cvt.u32.u64 %0, t; }"
        : "=r"(a) : "l"(p));
    return a;
}
__device__ __forceinline__ void cp16(uint32_t d, const void* g) {
    asm volatile("cp.async.cg.shared.global [%0], [%1], 16;" :: "r"(d), "l"(g));
}
__device__ __forceinline__ void ldsm4(uint32_t* r, uint32_t a) {
    asm volatile("ldmatrix.sync.aligned.m8n8.x4.shared.b16 {%0,%1,%2,%3}, [%4];"
        : "=r"(r[0]), "=r"(r[1]), "=r"(r[2]), "=r"(r[3]) : "r"(a));
}
__device__ __forceinline__ void ldsm4t(uint32_t* r, uint32_t a) {
    asm volatile("ldmatrix.sync.aligned.m8n8.x4.trans.shared.b16 {%0,%1,%2,%3}, [%4];"
        : "=r"(r[0]), "=r"(r[1]), "=r"(r[2]), "=r"(r[3]) : "r"(a));
}
__device__ __forceinline__ void mma16816(float* c, const uint32_t* a, const uint32_t* b) {
    asm volatile("mma.sync.aligned.m16n8k16.row.col.f32.f16.f16.f32 "
        "{%0,%1,%2,%3}, {%4,%5,%6,%7}, {%8,%9}, {%0,%1,%2,%3};"
        : "+f"(c[0]), "+f"(c[1]), "+f"(c[2]), "+f"(c[3])
        : "r"(a[0]), "r"(a[1]), "r"(a[2]), "r"(a[3]), "r"(b[0]), "r"(b[1]));
}
__device__ __forceinline__ uint32_t h2pack(float a, float b) {
    __half2 h = __floats2half2_rn(a, b);
    return *(uint32_t*)&h;
}
#define CP_COMMIT() asm volatile("cp.async.commit_group;" ::: "memory")
#define CP_WAIT1()  asm volatile("cp.async.wait_group 1;" ::: "memory")

// ---------------------------------------------------------------------------
// fp32 -> fp16 convert
// ---------------------------------------------------------------------------
__global__ __launch_bounds__(256) void convert_kernel(const float* __restrict__ in,
                                                      __half* __restrict__ out,
                                                      int n4) {
    int i = blockIdx.x * blockDim.x + threadIdx.x;
    if (i >= n4) return;
    float4 v = ((const float4*)in)[i];
    ((uint32_t*)out)[2 * i]     = h2pack(v.x, v.y);
    ((uint32_t*)out)[2 * i + 1] = h2pack(v.z, v.w);
}

// ---------------------------------------------------------------------------
// Single-pass fp16 GEMM: C[m,n] = sum_k A[m,k]*B[n,k] + bias[n]
// Stage = {A, B} 128x64 fp16 tiles, 144B pitch (conflict-free ldsm),
// 36.9KB/stage, GS=2 -> 74KB/CTA, 2 CTA/SM. 16 iterations of BK=64.
// ---------------------------------------------------------------------------
#define GP 144
#define GTILE_B (128 * GP)        // 18432
#define GSTAGE_B (2 * GTILE_B)    // 36864
#define GNIT 16

__device__ __forceinline__ void load_stage2(uint32_t st,
                                            const __half* __restrict__ A,
                                            const __half* __restrict__ B,
                                            int m0, int n0, int kk, int tid) {
    #pragma unroll
    for (int t = 0; t < 4; t++) {
        const int chunk = tid + t * 256;     // 0..1023
        const int row = chunk >> 3;          // 0..127
        const int ch  = chunk & 7;           // 16B chunk within 128B row
        const uint32_t off = row * GP + ch * 16;
        cp16(st + off,           A + (size_t)(m0 + row) * DD + kk + ch * 8);
        cp16(st + GTILE_B + off, B + (size_t)(n0 + row) * DD + kk + ch * 8);
    }
}

__device__ __forceinline__ void gemm_mainloop(uint32_t sbase,
                                              const __half* __restrict__ A,
                                              const __half* __restrict__ B,
                                              int m0, int n0, int tid,
                                              float (&acc)[2][8][4]) {
    const int lane = tid & 31;
    const int warp = tid >> 5;
    const int wm = warp >> 1;
    const int wn = warp & 1;
    const int l_sub = lane & 15;
    const int l_cc  = lane >> 4;

    load_stage2(sbase, A, B, m0, n0, 0, tid);
    CP_COMMIT();
    load_stage2(sbase + GSTAGE_B, A, B, m0, n0, 64, tid);
    CP_COMMIT();

    for (int it = 0; it < GNIT; it++) {
        const uint32_t st = sbase + (it & 1) * GSTAGE_B;
        CP_WAIT1();
        __syncthreads();

        #pragma unroll
        for (int kk = 0; kk < 4; kk++) {
            const int cc = kk * 2 + l_cc;
            uint32_t a[2][4], b[8][2];
            #pragma unroll
            for (int i = 0; i < 2; i++) {
                const uint32_t ro = (wm * 32 + i * 16 + l_sub) * GP + cc * 16;
                ldsm4(a[i], st + ro);
            }
            #pragma unroll
            for (int j2 = 0; j2 < 4; j2++) {
                const uint32_t ro = GTILE_B + (wn * 64 + j2 * 16 + l_sub) * GP + cc * 16;
                uint32_t r[4];
                ldsm4(r, st + ro);
                b[j2 * 2][0] = r[0];     b[j2 * 2][1] = r[2];
                b[j2 * 2 + 1][0] = r[1]; b[j2 * 2 + 1][1] = r[3];
            }
            #pragma unroll
            for (int i = 0; i < 2; i++)
                #pragma unroll
                for (int j = 0; j < 8; j++)
                    mma16816(acc[i][j], a[i], b[j]);
        }

        __syncthreads();
        if (it + 2 < GNIT)
            load_stage2(st, A, B, m0, n0, (it + 2) << 6, tid);
        CP_COMMIT();
    }
}

// ---- qkv GEMM: scatter epilogue -> q/k/v fp16 in [b,h,t,d] (q scaled) ----
__global__ __launch_bounds__(256, 2)
void qkv_gemm_kernel(const __half* __restrict__ A,
                     const __half* __restrict__ B,
                     const float* __restrict__ bias,
                     __half* __restrict__ q16, __half* __restrict__ k16,
                     __half* __restrict__ v16) {
    extern __shared__ __align__(1024) char sm[];
    const uint32_t sbase = smem_u32(sm);
    const int tid = threadIdx.x;
    const int lane = tid & 31;
    const int warp = tid >> 5;
    const int wm = warp >> 1, wn = warp & 1;
    const int m0 = blockIdx.y * 128;
    const int n0 = blockIdx.x * 128;

    float acc[2][8][4];
    #pragma unroll
    for (int i = 0; i < 2; i++)
        #pragma unroll
        for (int j = 0; j < 8; j++)
            #pragma unroll
            for (int r = 0; r < 4; r++) acc[i][j][r] = 0.f;

    gemm_mainloop(sbase, A, B, m0, n0, tid, acc);

    const int l4 = lane >> 2;
    const int l2 = (lane & 3) << 1;
    #pragma unroll
    for (int i = 0; i < 2; i++) {
        const int row = m0 + wm * 32 + i * 16 + l4;   // token index
        const int bi = row >> 11;
        const int t  = row & 2047;
        #pragma unroll
        for (int j = 0; j < 8; j++) {
            const int col = n0 + wn * 64 + j * 8 + l2;
            const int type = col >> 10;
            const int hc = (col & 1023) >> 6;
            const int d  = col & 63;
            const float2 bv = *(const float2*)(bias + col);
            float v0 = acc[i][j][0] + bv.x, v1 = acc[i][j][1] + bv.y;
            float v2 = acc[i][j][2] + bv.x, v3 = acc[i][j][3] + bv.y;
            if (type == 0) { v0 *= 0.125f; v1 *= 0.125f; v2 *= 0.125f; v3 *= 0.125f; }
            __half* dst = (type == 0) ? q16 : (type == 1) ? k16 : v16;
            const size_t off0 = (((size_t)(bi * HH + hc)) * TT + t) * 64 + d;
            const size_t off1 = off0 + 8 * 64;
            ((uint32_t*)dst)[off0 >> 1] = h2pack(v0, v1);
            ((uint32_t*)dst)[off1 >> 1] = h2pack(v2, v3);
        }
    }
}

// ---- proj GEMM: fp32 epilogue ----
__global__ __launch_bounds__(256, 2)
void proj_gemm_kernel(const __half* __restrict__ A,
                      const __half* __restrict__ B,
                      const float* __restrict__ bias,
                      float* __restrict__ C, int ldc) {
    extern __shared__ __align__(1024) char sm[];
    const uint32_t sbase = smem_u32(sm);
    const int tid = threadIdx.x;
    const int lane = tid & 31;
    const int warp = tid >> 5;
    const int wm = warp >> 1, wn = warp & 1;
    const int m0 = blockIdx.y * 128;
    const int n0 = blockIdx.x * 128;

    float acc[2][8][4];
    #pragma unroll
    for (int i = 0; i < 2; i++)
        #pragma unroll
        for (int j = 0; j < 8; j++)
            #pragma unroll
            for (int r = 0; r < 4; r++) acc[i][j][r] = 0.f;

    gemm_mainloop(sbase, A, B, m0, n0, tid, acc);

    const int l4 = lane >> 2;
    const int l2 = (lane & 3) << 1;
    #pragma unroll
    for (int i = 0; i < 2; i++) {
        const int row0 = m0 + wm * 32 + i * 16 + l4;
        #pragma unroll
        for (int j = 0; j < 8; j++) {
            const int col = n0 + wn * 64 + j * 8 + l2;
            const float2 bv = *(const float2*)(bias + col);
            float2 v0, v1;
            v0.x = acc[i][j][0] + bv.x; v0.y = acc[i][j][1] + bv.y;
            v1.x = acc[i][j][2] + bv.x; v1.y = acc[i][j][3] + bv.y;
            *(float2*)(C + (size_t)row0 * ldc + col) = v0;
            *(float2*)(C + (size_t)(row0 + 8) * ldc + col) = v1;
        }
    }
}

// ---------------------------------------------------------------------------
// Flash attention on mma.sync, single-pass fp16.
// CTA = 128 q rows x (head, batch), 256 threads, kv tiles of 64
// double-buffered. smem 55KB -> 2 CTA/SM (16 warps/SM).
// ---------------------------------------------------------------------------
#define AP 144
#define Q_BYTES (128 * AP)           // 18432
#define KV_TILE_B (64 * AP)          // 9216
#define KV_STAGE_B (2 * KV_TILE_B)   // 18432 (K + V)
#define ATT_SMEM (Q_BYTES + 2 * KV_STAGE_B)  // 55296

__global__ __launch_bounds__(256, 2)
void attn_mma_kernel(const __half* __restrict__ q16, const __half* __restrict__ k16,
                     const __half* __restrict__ v16, __half* __restrict__ y16) {
    extern __shared__ __align__(1024) char sm[];
    const uint32_t sb = smem_u32(sm);

    const int qi = blockIdx.x;
    const int h  = blockIdx.y;
    const int b  = blockIdx.z;
    const int q0 = qi * 128;
    const size_t base = ((size_t)(b * HH + h)) * TT * 64;

    const int tid  = threadIdx.x;
    const int warp = tid >> 5;
    const int lane = tid & 31;
    const int l_sub = lane & 15;
    const int l_cc  = lane >> 4;
    const int lq = lane >> 2;
    const int lr = lane & 3;

    // ---- stage Q ----
    #pragma unroll
    for (int t2 = 0; t2 < 4; t2++) {
        const int idx = tid + t2 * 256;   // 0..1023
        const int row = idx >> 3, ch = idx & 7;
        cp16(sb + row * AP + ch * 16, q16 + base + (size_t)(q0 + row) * 64 + ch * 8);
    }
    CP_COMMIT();

    const int nt = 2 * qi + 2;
    auto load_kv = [&](int s, int k0) {
        const uint32_t st = sb + Q_BYTES + s * KV_STAGE_B;
        const size_t srcb = base + (size_t)k0 * 64;
        #pragma unroll
        for (int t2 = 0; t2 < 2; t2++) {
            const int idx = tid + t2 * 256;  // 0..511
            const int row = idx >> 3, ch = idx & 7;
            const uint32_t off = row * AP + ch * 16;
            const size_t g = srcb + (size_t)row * 64 + ch * 8;
            cp16(st + off, k16 + g);
            cp16(st + KV_TILE_B + off, v16 + g);
        }
    };
    load_kv(0, 0);
    CP_COMMIT();

    CP_WAIT1();
    __syncthreads();

    // ---- Q fragments in registers ----
    uint32_t aq[4][4];
    #pragma unroll
    for (int kk = 0; kk < 4; kk++)
        ldsm4(aq[kk], sb + (warp * 16 + l_sub) * AP + (kk * 2 + l_cc) * 16);

    float m0r = -1e30f, m1r = -1e30f, l0 = 0.f, l1 = 0.f;
    float o[8][4];
    #pragma unroll
    for (int j = 0; j < 8; j++)
        #pragma unroll
        for (int r = 0; r < 4; r++) o[j][r] = 0.f;

    const int r0g = q0 + warp * 16 + lq;
    const int r1g = r0g + 8;
    const int rowmaxw = q0 + warp * 16 + 15;

    for (int kt = 0; kt < nt; kt++) {
        const int k0 = kt * 64;
        if (kt + 1 < nt) load_kv((kt + 1) & 1, (kt + 1) * 64);
        CP_COMMIT();
        CP_WAIT1();
        __syncthreads();

        if (k0 <= rowmaxw) {
            const uint32_t st = sb + Q_BYTES + (kt & 1) * KV_STAGE_B;

            // ---- S = Q K^T ----
            float s[8][4];
            #pragma unroll
            for (int j = 0; j < 8; j++)
                #pragma unroll
                for (int r = 0; r < 4; r++) s[j][r] = 0.f;

            #pragma unroll
            for (int kk = 0; kk < 4; kk++) {
                uint32_t bk[8][2];
                #pragma unroll
                for (int j2 = 0; j2 < 4; j2++) {
                    uint32_t r[4];
                    ldsm4(r, st + (j2 * 16 + l_sub) * AP + (kk * 2 + l_cc) * 16);
                    bk[j2 * 2][0] = r[0];     bk[j2 * 2][1] = r[2];
                    bk[j2 * 2 + 1][0] = r[1]; bk[j2 * 2 + 1][1] = r[3];
                }
                #pragma unroll
                for (int j = 0; j < 8; j++) mma16816(s[j], aq[kk], bk[j]);
            }

            // ---- causal mask (diagonal tiles) ----
            if (k0 + 63 > q0 + warp * 16) {
                #pragma unroll
                for (int j = 0; j < 8; j++) {
                    const int c = k0 + 8 * j + 2 * lr;
                    if (c > r0g)     s[j][0] = -1e30f;
                    if (c + 1 > r0g) s[j][1] = -1e30f;
                    if (c > r1g)     s[j][2] = -1e30f;
                    if (c + 1 > r1g) s[j][3] = -1e30f;
                }
            }

            // ---- online softmax ----
            float mx0 = -1e30f, mx1 = -1e30f;
            #pragma unroll
            for (int j = 0; j < 8; j++) {
                mx0 = fmaxf(mx0, fmaxf(s[j][0], s[j][1]));
                mx1 = fmaxf(mx1, fmaxf(s[j][2], s[j][3]));
            }
            #pragma unroll
            for (int off = 1; off <= 2; off <<= 1) {
                mx0 = fmaxf(mx0, __shfl_xor_sync(0xffffffffu, mx0, off));
                mx1 = fmaxf(mx1, __shfl_xor_sync(0xffffffffu, mx1, off));
            }
            const float mn0 = fmaxf(m0r, mx0), mn1 = fmaxf(m1r, mx1);
            const float c0 = __expf(m0r - mn0), c1 = __expf(m1r - mn1);
            m0r = mn0; m1r = mn1;

            float rs0 = 0.f, rs1 = 0.f;
            #pragma unroll
            for (int j = 0; j < 8; j++) {
                s[j][0] = __expf(s[j][0] - mn0);
                s[j][1] = __expf(s[j][1] - mn0);
                s[j][2] = __expf(s[j][2] - mn1);
                s[j][3] = __expf(s[j][3] - mn1);
                rs0 += s[j][0] + s[j][1];
                rs1 += s[j][2] + s[j][3];
            }
            #pragma unroll
            for (int off = 1; off <= 2; off <<= 1) {
                rs0 += __shfl_xor_sync(0xffffffffu, rs0, off);
                rs1 += __shfl_xor_sync(0xffffffffu, rs1, off);
            }
            l0 = l0 * c0 + rs0;
            l1 = l1 * c1 + rs1;
            #pragma unroll
            for (int j = 0; j < 8; j++) {
                o[j][0] *= c0; o[j][1] *= c0;
                o[j][2] *= c1; o[j][3] *= c1;
            }

            // ---- O += P V (P -> fp16 A frags straight from acc) ----
            #pragma unroll
            for (int kg = 0; kg < 4; kg++) {
                uint32_t ap[4];
                ap[0] = h2pack(s[2 * kg][0], s[2 * kg][1]);
                ap[1] = h2pack(s[2 * kg][2], s[2 * kg][3]);
                ap[2] = h2pack(s[2 * kg + 1][0], s[2 * kg + 1][1]);
                ap[3] = h2pack(s[2 * kg + 1][2], s[2 * kg + 1][3]);

                const int mm = lane >> 3;
                const int rowv = kg * 16 + (mm & 1) * 8 + (lane & 7);
                const int chb = mm >> 1;

                uint32_t bv[8][2];
                #pragma unroll
                for (int dg = 0; dg < 4; dg++) {
                    uint32_t r[4];
                    ldsm4t(r, st + KV_TILE_B + rowv * AP + (dg * 2 + chb) * 16);
                    bv[dg * 2][0] = r[0];     bv[dg * 2][1] = r[1];
                    bv[dg * 2 + 1][0] = r[2]; bv[dg * 2 + 1][1] = r[3];
                }
                #pragma unroll
                for (int jn = 0; jn < 8; jn++) mma16816(o[jn], ap, bv[jn]);
            }
        }
        __syncthreads();
    }

    // ---- epilogue: normalize, write y fp16 in [token][D] ----
    const float inv0 = 1.0f / l0;
    const float inv1 = 1.0f / l1;
    const size_t tok0 = (size_t)(b * TT + q0 + warp * 16 + lq);
    const size_t tok1 = tok0 + 8;
    #pragma unroll
    for (int jn = 0; jn < 8; jn++) {
        const int d = 8 * jn + 2 * lr;
        ((uint32_t*)y16)[(tok0 * DD + h * 64 + d) >> 1] = h2pack(o[jn][0] * inv0, o[jn][1] * inv0);
        ((uint32_t*)y16)[(tok1 * DD + h * 64 + d) >> 1] = h2pack(o[jn][2] * inv1, o[jn][3] * inv1);
    }
}

// ---------------------------------------------------------------------------
// Host side
// ---------------------------------------------------------------------------
extern "C" void kernel_launch(void* const* d_in, const int* in_sizes, int n_in,
                              void* d_out, int out_size) {
    const float* x      = (const float*)d_in[0];
    const float* w_qkv  = (const float*)d_in[2];
    const float* b_qkv  = (const float*)d_in[3];
    const float* w_proj = (const float*)d_in[4];
    const float* b_proj = (const float*)d_in[5];
    float* out = (float*)d_out;

    void *px, *pwq, *pwp, *py, *pq, *pk, *pv;
    cudaGetSymbolAddress(&px, g_x16);
    cudaGetSymbolAddress(&pwq, g_wq16);
    cudaGetSymbolAddress(&pwp, g_wp16);
    cudaGetSymbolAddress(&py, g_y16);
    cudaGetSymbolAddress(&pq, g_q16);
    cudaGetSymbolAddress(&pk, g_k16);
    cudaGetSymbolAddress(&pv, g_v16);

    static int attr_set = 0;
    if (!attr_set) {
        cudaFuncSetAttribute(qkv_gemm_kernel,
                             cudaFuncAttributeMaxDynamicSharedMemorySize, 2 * GSTAGE_B);
        cudaFuncSetAttribute(proj_gemm_kernel,
                             cudaFuncAttributeMaxDynamicSharedMemorySize, 2 * GSTAGE_B);
        cudaFuncSetAttribute(attn_mma_kernel,
                             cudaFuncAttributeMaxDynamicSharedMemorySize, ATT_SMEM);
        attr_set = 1;
    }

    // 1) convert inputs to fp16
    convert_kernel<<<(MROWS * DD) / 1024, 256>>>(x, (__half*)px, (MROWS * DD) / 4);
    convert_kernel<<<(3 * DD * DD) / 1024, 256>>>(w_qkv, (__half*)pwq, (3 * DD * DD) / 4);
    convert_kernel<<<(DD * DD) / 1024, 256>>>(w_proj, (__half*)pwp, (DD * DD) / 4);

    // 2) QKV GEMM -> q/k/v fp16 in [b,h,t,d] (q pre-scaled by 1/8)
    {
        dim3 grid((3 * DD) / 128, MROWS / 128);
        qkv_gemm_kernel<<<grid, 256, 2 * GSTAGE_B>>>(
            (const __half*)px, (const __half*)pwq, b_qkv,
            (__half*)pq, (__half*)pk, (__half*)pv);
    }

    // 3) flash attention (mma.sync fp16) -> y fp16
    {
        dim3 grid(TT / 128, HH, BB);
        attn_mma_kernel<<<grid, 256, ATT_SMEM>>>(
            (const __half*)pq, (const __half*)pk, (const __half*)pv, (__half*)py);
    }

    // 4) output projection -> out (fp32)
    {
        dim3 grid(DD / 128, MROWS / 128);
        proj_gemm_kernel<<<grid, 256, 2 * GSTAGE_B>>>(
            (const __half*)py, (const __half*)pwp, b_proj, out, DD);
    }
}

// round 13
// speedup vs baseline: 2.7585x; 1.0199x over previous
#include <cuda_runtime.h>
#include <cuda_fp16.h>
#include <cstdint>
#include <math.h>

#define BB 2
#define TT 2048
#define DD 1024
#define HH 16
#define HDIM 64
#define MROWS (BB * TT)   // 4096

// ---------------------------------------------------------------------------
// Scratch (device globals; no allocation anywhere). All fp16 single-pass.
// ---------------------------------------------------------------------------
__device__ __align__(256) __half g_x16[(size_t)MROWS * DD];
__device__ __align__(256) __half g_wq16[(size_t)3 * DD * DD];
__device__ __align__(256) __half g_wp16[(size_t)DD * DD];
__device__ __align__(256) __half g_y16[(size_t)MROWS * DD];
// q/k/v in [b,h,t,d] layout
__device__ __align__(256) __half g_q16[(size_t)MROWS * DD];
__device__ __align__(256) __half g_k16[(size_t)MROWS * DD];
__device__ __align__(256) __half g_v16[(size_t)MROWS * DD];

// ---------------------------------------------------------------------------
// helpers
// ---------------------------------------------------------------------------
__device__ __forceinline__ uint32_t smem_u32(const void* p) {
    uint32_t a;
    asm("{ .reg .u64 t; cvta.to.shared.u64 t, %1; cvt.u32.u64 %0, t; }"
        : "=r"(a) : "l"(p));
    return a;
}
__device__ __forceinline__ void cp16(uint32_t d, const void* g) {
    asm volatile("cp.async.cg.shared.global [%0], [%1], 16;" :: "r"(d), "l"(g));
}
__device__ __forceinline__ void ldsm4(uint32_t* r, uint32_t a) {
    asm volatile("ldmatrix.sync.aligned.m8n8.x4.shared.b16 {%0,%1,%2,%3}, [%4];"
        : "=r"(r[0]), "=r"(r[1]), "=r"(r[2]), "=r"(r[3]) : "r"(a));
}
__device__ __forceinline__ void ldsm4t(uint32_t* r, uint32_t a) {
    asm volatile("ldmatrix.sync.aligned.m8n8.x4.trans.shared.b16 {%0,%1,%2,%3}, [%4];"
        : "=r"(r[0]), "=r"(r[1]), "=r"(r[2]), "=r"(r[3]) : "r"(a));
}
__device__ __forceinline__ void mma16816(float* c, const uint32_t* a, const uint32_t* b) {
    asm volatile("mma.sync.aligned.m16n8k16.row.col.f32.f16.f16.f32 "
        "{%0,%1,%2,%3}, {%4,%5,%6,%7}, {%8,%9}, {%0,%1,%2,%3};"
        : "+f"(c[0]), "+f"(c[1]), "+f"(c[2]), "+f"(c[3])
        : "r"(a[0]), "r"(a[1]), "r"(a[2]), "r"(a[3]), "r"(b[0]), "r"(b[1]));
}
__device__ __forceinline__ uint32_t h2pack(float a, float b) {
    __half2 h = __floats2half2_rn(a, b);
    return *(uint32_t*)&h;
}
#define CP_COMMIT() asm volatile("cp.async.commit_group;" ::: "memory")
#define CP_WAIT1()  asm volatile("cp.async.wait_group 1;" ::: "memory")

// ---------------------------------------------------------------------------
// fp32 -> fp16 convert
// ---------------------------------------------------------------------------
__global__ __launch_bounds__(256) void convert_kernel(const float* __restrict__ in,
                                                      __half* __restrict__ out,
                                                      int n4) {
    int i = blockIdx.x * blockDim.x + threadIdx.x;
    if (i >= n4) return;
    float4 v = ((const float4*)in)[i];
    ((uint32_t*)out)[2 * i]     = h2pack(v.x, v.y);
    ((uint32_t*)out)[2 * i + 1] = h2pack(v.z, v.w);
}

// ---------------------------------------------------------------------------
// Single-pass fp16 GEMM: C[m,n] = sum_k A[m,k]*B[n,k] + bias[n]
// Stage = {A, B} 128x64 fp16 tiles, 144B pitch, 36.9KB/stage.
// 3-slot ring, 2 stages in flight: refill of stage it+2 targets the slot
// consumed at it-1 -> refill BEFORE compute, ONE barrier per iteration.
// 111KB/CTA, 2 CTA/SM. 16 iterations of BK=64.
// ---------------------------------------------------------------------------
#define GP 144
#define GTILE_B (128 * GP)        // 18432
#define GSTAGE_B (2 * GTILE_B)    // 36864
#define GSMEM (3 * GSTAGE_B)      // 110592
#define GNIT 16

__device__ __forceinline__ void load_stage2(uint32_t st,
                                            const __half* __restrict__ A,
                                            const __half* __restrict__ B,
                                            int m0, int n0, int kk, int tid) {
    #pragma unroll
    for (int t = 0; t < 4; t++) {
        const int chunk = tid + t * 256;     // 0..1023
        const int row = chunk >> 3;          // 0..127
        const int ch  = chunk & 7;           // 16B chunk within 128B row
        const uint32_t off = row * GP + ch * 16;
        cp16(st + off,           A + (size_t)(m0 + row) * DD + kk + ch * 8);
        cp16(st + GTILE_B + off, B + (size_t)(n0 + row) * DD + kk + ch * 8);
    }
}

__device__ __forceinline__ void gemm_mainloop(uint32_t sbase,
                                              const __half* __restrict__ A,
                                              const __half* __restrict__ B,
                                              int m0, int n0, int tid,
                                              float (&acc)[2][8][4]) {
    const int lane = tid & 31;
    const int warp = tid >> 5;
    const int wm = warp >> 1;
    const int wn = warp & 1;
    const int l_sub = lane & 15;
    const int l_cc  = lane >> 4;

    // prologue: 2 stages in flight (slots 0, 1)
    load_stage2(sbase, A, B, m0, n0, 0, tid);
    CP_COMMIT();
    load_stage2(sbase + GSTAGE_B, A, B, m0, n0, 64, tid);
    CP_COMMIT();

    int slot = 0;
    for (int it = 0; it < GNIT; it++) {
        CP_WAIT1();              // stage it landed (it+1 may still fly)
        __syncthreads();         // all warps done with stage it-1

        // eager refill: slot (it+2)%3 was consumed at it-1 -> free now
        if (it + 2 < GNIT) {
            const int ns = (slot + 2 >= 3) ? slot - 1 : slot + 2;
            load_stage2(sbase + ns * GSTAGE_B, A, B, m0, n0, (it + 2) << 6, tid);
        }
        CP_COMMIT();

        const uint32_t st = sbase + slot * GSTAGE_B;

        #pragma unroll
        for (int kk = 0; kk < 4; kk++) {
            const int cc = kk * 2 + l_cc;
            uint32_t a[2][4], b[8][2];
            #pragma unroll
            for (int i = 0; i < 2; i++) {
                const uint32_t ro = (wm * 32 + i * 16 + l_sub) * GP + cc * 16;
                ldsm4(a[i], st + ro);
            }
            #pragma unroll
            for (int j2 = 0; j2 < 4; j2++) {
                const uint32_t ro = GTILE_B + (wn * 64 + j2 * 16 + l_sub) * GP + cc * 16;
                uint32_t r[4];
                ldsm4(r, st + ro);
                b[j2 * 2][0] = r[0];     b[j2 * 2][1] = r[2];
                b[j2 * 2 + 1][0] = r[1]; b[j2 * 2 + 1][1] = r[3];
            }
            #pragma unroll
            for (int i = 0; i < 2; i++)
                #pragma unroll
                for (int j = 0; j < 8; j++)
                    mma16816(acc[i][j], a[i], b[j]);
        }

        slot = (slot + 1 == 3) ? 0 : slot + 1;
    }
}

// ---- qkv GEMM: scatter epilogue -> q/k/v fp16 in [b,h,t,d] (q scaled) ----
__global__ __launch_bounds__(256, 2)
void qkv_gemm_kernel(const __half* __restrict__ A,
                     const __half* __restrict__ B,
                     const float* __restrict__ bias,
                     __half* __restrict__ q16, __half* __restrict__ k16,
                     __half* __restrict__ v16) {
    extern __shared__ __align__(1024) char sm[];
    const uint32_t sbase = smem_u32(sm);
    const int tid = threadIdx.x;
    const int lane = tid & 31;
    const int warp = tid >> 5;
    const int wm = warp >> 1, wn = warp & 1;
    const int m0 = blockIdx.y * 128;
    const int n0 = blockIdx.x * 128;

    float acc[2][8][4];
    #pragma unroll
    for (int i = 0; i < 2; i++)
        #pragma unroll
        for (int j = 0; j < 8; j++)
            #pragma unroll
            for (int r = 0; r < 4; r++) acc[i][j][r] = 0.f;

    gemm_mainloop(sbase, A, B, m0, n0, tid, acc);

    const int l4 = lane >> 2;
    const int l2 = (lane & 3) << 1;
    #pragma unroll
    for (int i = 0; i < 2; i++) {
        const int row = m0 + wm * 32 + i * 16 + l4;   // token index
        const int bi = row >> 11;
        const int t  = row & 2047;
        #pragma unroll
        for (int j = 0; j < 8; j++) {
            const int col = n0 + wn * 64 + j * 8 + l2;
            const int type = col >> 10;
            const int hc = (col & 1023) >> 6;
            const int d  = col & 63;
            const float2 bv = *(const float2*)(bias + col);
            float v0 = acc[i][j][0] + bv.x, v1 = acc[i][j][1] + bv.y;
            float v2 = acc[i][j][2] + bv.x, v3 = acc[i][j][3] + bv.y;
            if (type == 0) { v0 *= 0.125f; v1 *= 0.125f; v2 *= 0.125f; v3 *= 0.125f; }
            __half* dst = (type == 0) ? q16 : (type == 1) ? k16 : v16;
            const size_t off0 = (((size_t)(bi * HH + hc)) * TT + t) * 64 + d;
            const size_t off1 = off0 + 8 * 64;
            ((uint32_t*)dst)[off0 >> 1] = h2pack(v0, v1);
            ((uint32_t*)dst)[off1 >> 1] = h2pack(v2, v3);
        }
    }
}

// ---- proj GEMM: fp32 epilogue ----
__global__ __launch_bounds__(256, 2)
void proj_gemm_kernel(const __half* __restrict__ A,
                      const __half* __restrict__ B,
                      const float* __restrict__ bias,
                      float* __restrict__ C, int ldc) {
    extern __shared__ __align__(1024) char sm[];
    const uint32_t sbase = smem_u32(sm);
    const int tid = threadIdx.x;
    const int lane = tid & 31;
    const int warp = tid >> 5;
    const int wm = warp >> 1, wn = warp & 1;
    const int m0 = blockIdx.y * 128;
    const int n0 = blockIdx.x * 128;

    float acc[2][8][4];
    #pragma unroll
    for (int i = 0; i < 2; i++)
        #pragma unroll
        for (int j = 0; j < 8; j++)
            #pragma unroll
            for (int r = 0; r < 4; r++) acc[i][j][r] = 0.f;

    gemm_mainloop(sbase, A, B, m0, n0, tid, acc);

    const int l4 = lane >> 2;
    const int l2 = (lane & 3) << 1;
    #pragma unroll
    for (int i = 0; i < 2; i++) {
        const int row0 = m0 + wm * 32 + i * 16 + l4;
        #pragma unroll
        for (int j = 0; j < 8; j++) {
            const int col = n0 + wn * 64 + j * 8 + l2;
            const float2 bv = *(const float2*)(bias + col);
            float2 v0, v1;
            v0.x = acc[i][j][0] + bv.x; v0.y = acc[i][j][1] + bv.y;
            v1.x = acc[i][j][2] + bv.x; v1.y = acc[i][j][3] + bv.y;
            *(float2*)(C + (size_t)row0 * ldc + col) = v0;
            *(float2*)(C + (size_t)(row0 + 8) * ldc + col) = v1;
        }
    }
}

// ---------------------------------------------------------------------------
// Flash attention on mma.sync, single-pass fp16.
// CTA = 128 q rows x (head, batch), 256 threads. kv: 3-slot ring, 2 stages
// in flight, eager refill, ONE barrier per iteration. smem 73.7KB, 2 CTA/SM.
// ---------------------------------------------------------------------------
#define AP 144
#define Q_BYTES (128 * AP)           // 18432
#define KV_TILE_B (64 * AP)          // 9216
#define KV_STAGE_B (2 * KV_TILE_B)   // 18432 (K + V)
#define ATT_SMEM (Q_BYTES + 3 * KV_STAGE_B)  // 73728

__global__ __launch_bounds__(256, 2)
void attn_mma_kernel(const __half* __restrict__ q16, const __half* __restrict__ k16,
                     const __half* __restrict__ v16, __half* __restrict__ y16) {
    extern __shared__ __align__(1024) char sm[];
    const uint32_t sb = smem_u32(sm);

    const int qi = blockIdx.x;
    const int h  = blockIdx.y;
    const int b  = blockIdx.z;
    const int q0 = qi * 128;
    const size_t base = ((size_t)(b * HH + h)) * TT * 64;

    const int tid  = threadIdx.x;
    const int warp = tid >> 5;
    const int lane = tid & 31;
    const int l_sub = lane & 15;
    const int l_cc  = lane >> 4;
    const int lq = lane >> 2;
    const int lr = lane & 3;

    const int nt = 2 * qi + 2;
    auto load_kv = [&](int s, int k0) {
        const uint32_t st = sb + Q_BYTES + s * KV_STAGE_B;
        const size_t srcb = base + (size_t)k0 * 64;
        #pragma unroll
        for (int t2 = 0; t2 < 2; t2++) {
            const int idx = tid + t2 * 256;  // 0..511
            const int row = idx >> 3, ch = idx & 7;
            const uint32_t off = row * AP + ch * 16;
            const size_t g = srcb + (size_t)row * 64 + ch * 8;
            cp16(st + off, k16 + g);
            cp16(st + KV_TILE_B + off, v16 + g);
        }
    };

    // ---- prologue: group0 = Q + kv0, group1 = kv1 ----
    #pragma unroll
    for (int t2 = 0; t2 < 4; t2++) {
        const int idx = tid + t2 * 256;   // 0..1023
        const int row = idx >> 3, ch = idx & 7;
        cp16(sb + row * AP + ch * 16, q16 + base + (size_t)(q0 + row) * 64 + ch * 8);
    }
    load_kv(0, 0);
    CP_COMMIT();
    if (nt > 1) load_kv(1, 64);
    CP_COMMIT();

    CP_WAIT1();
    __syncthreads();

    // ---- Q fragments in registers ----
    uint32_t aq[4][4];
    #pragma unroll
    for (int kk = 0; kk < 4; kk++)
        ldsm4(aq[kk], sb + (warp * 16 + l_sub) * AP + (kk * 2 + l_cc) * 16);

    float m0r = -1e30f, m1r = -1e30f, l0 = 0.f, l1 = 0.f;
    float o[8][4];
    #pragma unroll
    for (int j = 0; j < 8; j++)
        #pragma unroll
        for (int r = 0; r < 4; r++) o[j][r] = 0.f;

    const int r0g = q0 + warp * 16 + lq;
    const int r1g = r0g + 8;
    const int rowmaxw = q0 + warp * 16 + 15;

    int slot = 0;
    for (int kt = 0; kt < nt; kt++) {
        const int k0 = kt * 64;
        if (kt > 0) {            // stage kt already awaited at kt=0 prologue
            CP_WAIT1();
            __syncthreads();
        }

        // eager refill: slot (kt+2)%3 was consumed at kt-1 -> free now
        if (kt + 2 < nt) {
            const int ns = (slot + 2 >= 3) ? slot - 1 : slot + 2;
            load_kv(ns, (kt + 2) * 64);
        }
        CP_COMMIT();

        if (k0 <= rowmaxw) {
            const uint32_t st = sb + Q_BYTES + slot * KV_STAGE_B;

            // ---- S = Q K^T ----
            float s[8][4];
            #pragma unroll
            for (int j = 0; j < 8; j++)
                #pragma unroll
                for (int r = 0; r < 4; r++) s[j][r] = 0.f;

            #pragma unroll
            for (int kk = 0; kk < 4; kk++) {
                uint32_t bk[8][2];
                #pragma unroll
                for (int j2 = 0; j2 < 4; j2++) {
                    uint32_t r[4];
                    ldsm4(r, st + (j2 * 16 + l_sub) * AP + (kk * 2 + l_cc) * 16);
                    bk[j2 * 2][0] = r[0];     bk[j2 * 2][1] = r[2];
                    bk[j2 * 2 + 1][0] = r[1]; bk[j2 * 2 + 1][1] = r[3];
                }
                #pragma unroll
                for (int j = 0; j < 8; j++) mma16816(s[j], aq[kk], bk[j]);
            }

            // ---- causal mask (diagonal tiles) ----
            if (k0 + 63 > q0 + warp * 16) {
                #pragma unroll
                for (int j = 0; j < 8; j++) {
                    const int c = k0 + 8 * j + 2 * lr;
                    if (c > r0g)     s[j][0] = -1e30f;
                    if (c + 1 > r0g) s[j][1] = -1e30f;
                    if (c > r1g)     s[j][2] = -1e30f;
                    if (c + 1 > r1g) s[j][3] = -1e30f;
                }
            }

            // ---- online softmax ----
            float mx0 = -1e30f, mx1 = -1e30f;
            #pragma unroll
            for (int j = 0; j < 8; j++) {
                mx0 = fmaxf(mx0, fmaxf(s[j][0], s[j][1]));
                mx1 = fmaxf(mx1, fmaxf(s[j][2], s[j][3]));
            }
            #pragma unroll
            for (int off = 1; off <= 2; off <<= 1) {
                mx0 = fmaxf(mx0, __shfl_xor_sync(0xffffffffu, mx0, off));
                mx1 = fmaxf(mx1, __shfl_xor_sync(0xffffffffu, mx1, off));
            }
            const float mn0 = fmaxf(m0r, mx0), mn1 = fmaxf(m1r, mx1);
            const float c0 = __expf(m0r - mn0), c1 = __expf(m1r - mn1);
            m0r = mn0; m1r = mn1;

            float rs0 = 0.f, rs1 = 0.f;
            #pragma unroll
            for (int j = 0; j < 8; j++) {
                s[j][0] = __expf(s[j][0] - mn0);
                s[j][1] = __expf(s[j][1] - mn0);
                s[j][2] = __expf(s[j][2] - mn1);
                s[j][3] = __expf(s[j][3] - mn1);
                rs0 += s[j][0] + s[j][1];
                rs1 += s[j][2] + s[j][3];
            }
            #pragma unroll
            for (int off = 1; off <= 2; off <<= 1) {
                rs0 += __shfl_xor_sync(0xffffffffu, rs0, off);
                rs1 += __shfl_xor_sync(0xffffffffu, rs1, off);
            }
            l0 = l0 * c0 + rs0;
            l1 = l1 * c1 + rs1;
            #pragma unroll
            for (int j = 0; j < 8; j++) {
                o[j][0] *= c0; o[j][1] *= c0;
                o[j][2] *= c1; o[j][3] *= c1;
            }

            // ---- O += P V (P -> fp16 A frags straight from acc) ----
            #pragma unroll
            for (int kg = 0; kg < 4; kg++) {
                uint32_t ap[4];
                ap[0] = h2pack(s[2 * kg][0], s[2 * kg][1]);
                ap[1] = h2pack(s[2 * kg][2], s[2 * kg][3]);
                ap[2] = h2pack(s[2 * kg + 1][0], s[2 * kg + 1][1]);
                ap[3] = h2pack(s[2 * kg + 1][2], s[2 * kg + 1][3]);

                const int mm = lane >> 3;
                const int rowv = kg * 16 + (mm & 1) * 8 + (lane & 7);
                const int chb = mm >> 1;

                uint32_t bv[8][2];
                #pragma unroll
                for (int dg = 0; dg < 4; dg++) {
                    uint32_t r[4];
                    ldsm4t(r, st + KV_TILE_B + rowv * AP + (dg * 2 + chb) * 16);
                    bv[dg * 2][0] = r[0];     bv[dg * 2][1] = r[1];
                    bv[dg * 2 + 1][0] = r[2]; bv[dg * 2 + 1][1] = r[3];
                }
                #pragma unroll
                for (int jn = 0; jn < 8; jn++) mma16816(o[jn], ap, bv[jn]);
            }
        }

        slot = (slot + 1 == 3) ? 0 : slot + 1;
    }

    // ---- epilogue: normalize, write y fp16 in [token][D] ----
    const float inv0 = 1.0f / l0;
    const float inv1 = 1.0f / l1;
    const size_t tok0 = (size_t)(b * TT + q0 + warp * 16 + lq);
    const size_t tok1 = tok0 + 8;
    #pragma unroll
    for (int jn = 0; jn < 8; jn++) {
        const int d = 8 * jn + 2 * lr;
        ((uint32_t*)y16)[(tok0 * DD + h * 64 + d) >> 1] = h2pack(o[jn][0] * inv0, o[jn][1] * inv0);
        ((uint32_t*)y16)[(tok1 * DD + h * 64 + d) >> 1] = h2pack(o[jn][2] * inv1, o[jn][3] * inv1);
    }
}

// ---------------------------------------------------------------------------
// Host side
// ---------------------------------------------------------------------------
extern "C" void kernel_launch(void* const* d_in, const int* in_sizes, int n_in,
                              void* d_out, int out_size) {
    const float* x      = (const float*)d_in[0];
    const float* w_qkv  = (const float*)d_in[2];
    const float* b_qkv  = (const float*)d_in[3];
    const float* w_proj = (const float*)d_in[4];
    const float* b_proj = (const float*)d_in[5];
    float* out = (float*)d_out;

    void *px, *pwq, *pwp, *py, *pq, *pk, *pv;
    cudaGetSymbolAddress(&px, g_x16);
    cudaGetSymbolAddress(&pwq, g_wq16);
    cudaGetSymbolAddress(&pwp, g_wp16);
    cudaGetSymbolAddress(&py, g_y16);
    cudaGetSymbolAddress(&pq, g_q16);
    cudaGetSymbolAddress(&pk, g_k16);
    cudaGetSymbolAddress(&pv, g_v16);

    static int attr_set = 0;
    if (!attr_set) {
        cudaFuncSetAttribute(qkv_gemm_kernel,
                             cudaFuncAttributeMaxDynamicSharedMemorySize, GSMEM);
        cudaFuncSetAttribute(proj_gemm_kernel,
                             cudaFuncAttributeMaxDynamicSharedMemorySize, GSMEM);
        cudaFuncSetAttribute(attn_mma_kernel,
                             cudaFuncAttributeMaxDynamicSharedMemorySize, ATT_SMEM);
        attr_set = 1;
    }

    // 1) convert inputs to fp16
    convert_kernel<<<(MROWS * DD) / 1024, 256>>>(x, (__half*)px, (MROWS * DD) / 4);
    convert_kernel<<<(3 * DD * DD) / 1024, 256>>>(w_qkv, (__half*)pwq, (3 * DD * DD) / 4);
    convert_kernel<<<(DD * DD) / 1024, 256>>>(w_proj, (__half*)pwp, (DD * DD) / 4);

    // 2) QKV GEMM -> q/k/v fp16 in [b,h,t,d] (q pre-scaled by 1/8)
    {
        dim3 grid((3 * DD) / 128, MROWS / 128);
        qkv_gemm_kernel<<<grid, 256, GSMEM>>>(
            (const __half*)px, (const __half*)pwq, b_qkv,
            (__half*)pq, (__half*)pk, (__half*)pv);
    }

    // 3) flash attention (mma.sync fp16) -> y fp16
    {
        dim3 grid(TT / 128, HH, BB);
        attn_mma_kernel<<<grid, 256, ATT_SMEM>>>(
            (const __half*)pq, (const __half*)pk, (const __half*)pv, (__half*)py);
    }

    // 4) output projection -> out (fp32)
    {
        dim3 grid(DD / 128, MROWS / 128);
        proj_gemm_kernel<<<grid, 256, GSMEM>>>(
            (const __half*)py, (const __half*)pwp, b_proj, out, DD);
    }
}

// round 14
// speedup vs baseline: 2.8002x; 1.0151x over previous
#include <cuda_runtime.h>
#include <cuda_fp16.h>
#include <cstdint>
#include <math.h>

#define BB 2
#define TT 2048
#define DD 1024
#define HH 16
#define HDIM 64
#define MROWS (BB * TT)   // 4096

// ---------------------------------------------------------------------------
// Scratch (device globals; no allocation anywhere). All fp16 single-pass.
// ---------------------------------------------------------------------------
__device__ __align__(256) __half g_x16[(size_t)MROWS * DD];
__device__ __align__(256) __half g_wq16[(size_t)3 * DD * DD];
__device__ __align__(256) __half g_wp16[(size_t)DD * DD];
__device__ __align__(256) __half g_y16[(size_t)MROWS * DD];
__device__ __align__(256) __half g_q16[(size_t)MROWS * DD];
__device__ __align__(256) __half g_k16[(size_t)MROWS * DD];
__device__ __align__(256) __half g_v16[(size_t)MROWS * DD];

// ---------------------------------------------------------------------------
// helpers
// ---------------------------------------------------------------------------
__device__ __forceinline__ uint32_t smem_u32(const void* p) {
    uint32_t a;
    asm("{ .reg .u64 t; cvta.to.shared.u64 t, %1; cvt.u32.u64 %0, t; }"
        : "=r"(a) : "l"(p));
    return a;
}
__device__ __forceinline__ void cp16(uint32_t d, const void* g) {
    asm volatile("cp.async.cg.shared.global [%0], [%1], 16;" :: "r"(d), "l"(g));
}
__device__ __forceinline__ void ldsm4(uint32_t* r, uint32_t a) {
    asm volatile("ldmatrix.sync.aligned.m8n8.x4.shared.b16 {%0,%1,%2,%3}, [%4];"
        : "=r"(r[0]), "=r"(r[1]), "=r"(r[2]), "=r"(r[3]) : "r"(a));
}
__device__ __forceinline__ void ldsm4t(uint32_t* r, uint32_t a) {
    asm volatile("ldmatrix.sync.aligned.m8n8.x4.trans.shared.b16 {%0,%1,%2,%3}, [%4];"
        : "=r"(r[0]), "=r"(r[1]), "=r"(r[2]), "=r"(r[3]) : "r"(a));
}
__device__ __forceinline__ void mma16816(float* c, const uint32_t* a, const uint32_t* b) {
    asm volatile("mma.sync.aligned.m16n8k16.row.col.f32.f16.f16.f32 "
        "{%0,%1,%2,%3}, {%4,%5,%6,%7}, {%8,%9}, {%0,%1,%2,%3};"
        : "+f"(c[0]), "+f"(c[1]), "+f"(c[2]), "+f"(c[3])
        : "r"(a[0]), "r"(a[1]), "r"(a[2]), "r"(a[3]), "r"(b[0]), "r"(b[1]));
}
__device__ __forceinline__ uint32_t h2pack(float a, float b) {
    __half2 h = __floats2half2_rn(a, b);
    return *(uint32_t*)&h;
}
#define CP_COMMIT() asm volatile("cp.async.commit_group;" ::: "memory")
#define CP_WAIT1()  asm volatile("cp.async.wait_group 1;" ::: "memory")
#define CP_WAIT3()  asm volatile("cp.async.wait_group 3;" ::: "memory")

// ---------------------------------------------------------------------------
// fused fp32 -> fp16 convert for x, w_qkv, w_proj in one launch
// ---------------------------------------------------------------------------
__global__ __launch_bounds__(256) void convert3_kernel(
    const float* __restrict__ i0, __half* __restrict__ o0, int n0,
    const float* __restrict__ i1, __half* __restrict__ o1, int n1,
    const float* __restrict__ i2, __half* __restrict__ o2, int n2) {
    int i = blockIdx.x * blockDim.x + threadIdx.x;
    const float* in; __half* out; int j;
    if (i < n0) { in = i0; out = o0; j = i; }
    else if (i < n0 + n1) { in = i1; out = o1; j = i - n0; }
    else if (i < n0 + n1 + n2) { in = i2; out = o2; j = i - n0 - n1; }
    else return;
    float4 v = ((const float4*)in)[j];
    ((uint32_t*)out)[2 * j]     = h2pack(v.x, v.y);
    ((uint32_t*)out)[2 * j + 1] = h2pack(v.z, v.w);
}

// ---------------------------------------------------------------------------
// Single-pass fp16 GEMM: C[m,n] = sum_k A[m,k]*B[n,k] + bias[n]
// BK=32 stages; slot = {A,B} 128x32 tiles packed 2-rows-per-144B (ldsm
// conflict-free: banks 0,64,16,80,32,96,48,112 for rows 0..7).
// 6-slot ring, 4 stages in flight, refill targets slot consumed 2 iters ago
// -> __syncthreads only every OTHER iteration (warps may drift -> LDS/tensor
// phases of different warps overlap). 110.6KB/CTA, 2 CTA/SM, 32 iterations.
// ---------------------------------------------------------------------------
#define GTILE2 (64 * 144)        // 9216: 128 rows packed 2/144B
#define GSTAGE2 (2 * GTILE2)     // 18432
#define GSLOTS 6
#define GSMEM (GSLOTS * GSTAGE2) // 110592
#define GNIT2 32

__device__ __forceinline__ uint32_t g_off(int row, int ch) {
    return (uint32_t)((row >> 1) * 144 + (row & 1) * 64 + ch * 16);
}

__device__ __forceinline__ void load_stage2(uint32_t st,
                                            const __half* __restrict__ A,
                                            const __half* __restrict__ B,
                                            int m0, int n0, int kk, int tid) {
    #pragma unroll
    for (int t = 0; t < 2; t++) {
        const int idx = tid + t * 256;   // 0..511
        const int row = idx >> 2;        // 0..127
        const int ch  = idx & 3;         // 16B chunk within 64B k-row
        const uint32_t off = g_off(row, ch);
        cp16(st + off,          A + (size_t)(m0 + row) * DD + kk + ch * 8);
        cp16(st + GTILE2 + off, B + (size_t)(n0 + row) * DD + kk + ch * 8);
    }
}

__device__ __forceinline__ void gemm_mainloop(uint32_t sbase,
                                              const __half* __restrict__ A,
                                              const __half* __restrict__ B,
                                              int m0, int n0, int tid,
                                              float (&acc)[2][8][4]) {
    const int lane = tid & 31;
    const int warp = tid >> 5;
    const int wm = warp >> 1;
    const int wn = warp & 1;
    const int l_sub = lane & 15;
    const int l_cc  = lane >> 4;

    // prologue: 4 stages in flight (slots 0..3)
    #pragma unroll
    for (int s = 0; s < 4; s++) {
        load_stage2(sbase + s * GSTAGE2, A, B, m0, n0, s * 32, tid);
        CP_COMMIT();
    }

    int slot = 0;
    for (int it = 0; it < GNIT2; it++) {
        CP_WAIT3();                       // stage it landed
        if ((it & 1) == 0) __syncthreads();   // all warps finished it-1

        // refill slot consumed at it-2 (covered by the barrier in both parities)
        if (it + 4 < GNIT2) {
            int ns = slot + 4; if (ns >= GSLOTS) ns -= GSLOTS;
            load_stage2(sbase + ns * GSTAGE2, A, B, m0, n0, (it + 4) * 32, tid);
        }
        CP_COMMIT();

        const uint32_t st = sbase + slot * GSTAGE2;

        #pragma unroll
        for (int h = 0; h < 2; h++) {     // 2 k16 per BK=32
            const int cc = h * 2 + l_cc;
            uint32_t a[2][4], b[8][2];
            #pragma unroll
            for (int i = 0; i < 2; i++)
                ldsm4(a[i], st + g_off(wm * 32 + i * 16 + l_sub, cc));
            #pragma unroll
            for (int j2 = 0; j2 < 4; j2++) {
                uint32_t r[4];
                ldsm4(r, st + GTILE2 + g_off(wn * 64 + j2 * 16 + l_sub, cc));
                b[j2 * 2][0] = r[0];     b[j2 * 2][1] = r[2];
                b[j2 * 2 + 1][0] = r[1]; b[j2 * 2 + 1][1] = r[3];
            }
            #pragma unroll
            for (int i = 0; i < 2; i++)
                #pragma unroll
                for (int j = 0; j < 8; j++)
                    mma16816(acc[i][j], a[i], b[j]);
        }

        slot = (slot + 1 == GSLOTS) ? 0 : slot + 1;
    }
}

// ---- qkv GEMM: scatter epilogue -> q/k/v fp16 in [b,h,t,d] (q scaled) ----
__global__ __launch_bounds__(256, 2)
void qkv_gemm_kernel(const __half* __restrict__ A,
                     const __half* __restrict__ B,
                     const float* __restrict__ bias,
                     __half* __restrict__ q16, __half* __restrict__ k16,
                     __half* __restrict__ v16) {
    extern __shared__ __align__(1024) char sm[];
    const uint32_t sbase = smem_u32(sm);
    const int tid = threadIdx.x;
    const int lane = tid & 31;
    const int warp = tid >> 5;
    const int wm = warp >> 1, wn = warp & 1;
    const int m0 = blockIdx.y * 128;
    const int n0 = blockIdx.x * 128;

    float acc[2][8][4];
    #pragma unroll
    for (int i = 0; i < 2; i++)
        #pragma unroll
        for (int j = 0; j < 8; j++)
            #pragma unroll
            for (int r = 0; r < 4; r++) acc[i][j][r] = 0.f;

    gemm_mainloop(sbase, A, B, m0, n0, tid, acc);

    const int l4 = lane >> 2;
    const int l2 = (lane & 3) << 1;
    #pragma unroll
    for (int i = 0; i < 2; i++) {
        const int row = m0 + wm * 32 + i * 16 + l4;   // token index
        const int bi = row >> 11;
        const int t  = row & 2047;
        #pragma unroll
        for (int j = 0; j < 8; j++) {
            const int col = n0 + wn * 64 + j * 8 + l2;
            const int type = col >> 10;
            const int hc = (col & 1023) >> 6;
            const int d  = col & 63;
            const float2 bv = *(const float2*)(bias + col);
            float v0 = acc[i][j][0] + bv.x, v1 = acc[i][j][1] + bv.y;
            float v2 = acc[i][j][2] + bv.x, v3 = acc[i][j][3] + bv.y;
            if (type == 0) { v0 *= 0.125f; v1 *= 0.125f; v2 *= 0.125f; v3 *= 0.125f; }
            __half* dst = (type == 0) ? q16 : (type == 1) ? k16 : v16;
            const size_t off0 = (((size_t)(bi * HH + hc)) * TT + t) * 64 + d;
            const size_t off1 = off0 + 8 * 64;
            ((uint32_t*)dst)[off0 >> 1] = h2pack(v0, v1);
            ((uint32_t*)dst)[off1 >> 1] = h2pack(v2, v3);
        }
    }
}

// ---- proj GEMM: fp32 epilogue ----
__global__ __launch_bounds__(256, 2)
void proj_gemm_kernel(const __half* __restrict__ A,
                      const __half* __restrict__ B,
                      const float* __restrict__ bias,
                      float* __restrict__ C, int ldc) {
    extern __shared__ __align__(1024) char sm[];
    const uint32_t sbase = smem_u32(sm);
    const int tid = threadIdx.x;
    const int lane = tid & 31;
    const int warp = tid >> 5;
    const int wm = warp >> 1, wn = warp & 1;
    const int m0 = blockIdx.y * 128;
    const int n0 = blockIdx.x * 128;

    float acc[2][8][4];
    #pragma unroll
    for (int i = 0; i < 2; i++)
        #pragma unroll
        for (int j = 0; j < 8; j++)
            #pragma unroll
            for (int r = 0; r < 4; r++) acc[i][j][r] = 0.f;

    gemm_mainloop(sbase, A, B, m0, n0, tid, acc);

    const int l4 = lane >> 2;
    const int l2 = (lane & 3) << 1;
    #pragma unroll
    for (int i = 0; i < 2; i++) {
        const int row0 = m0 + wm * 32 + i * 16 + l4;
        #pragma unroll
        for (int j = 0; j < 8; j++) {
            const int col = n0 + wn * 64 + j * 8 + l2;
            const float2 bv = *(const float2*)(bias + col);
            float2 v0, v1;
            v0.x = acc[i][j][0] + bv.x; v0.y = acc[i][j][1] + bv.y;
            v1.x = acc[i][j][2] + bv.x; v1.y = acc[i][j][3] + bv.y;
            *(float2*)(C + (size_t)row0 * ldc + col) = v0;
            *(float2*)(C + (size_t)(row0 + 8) * ldc + col) = v1;
        }
    }
}

// ---------------------------------------------------------------------------
// Flash attention on mma.sync, single-pass fp16 (unchanged from R13 best).
// CTA = 128 q rows x (head, batch), 256 threads. kv: 3-slot ring, 2 stages
// in flight, eager refill, ONE barrier per iteration. 73.7KB, 2 CTA/SM.
// ---------------------------------------------------------------------------
#define AP 144
#define Q_BYTES (128 * AP)
#define KV_TILE_B (64 * AP)
#define KV_STAGE_B (2 * KV_TILE_B)
#define ATT_SMEM (Q_BYTES + 3 * KV_STAGE_B)

__global__ __launch_bounds__(256, 2)
void attn_mma_kernel(const __half* __restrict__ q16, const __half* __restrict__ k16,
                     const __half* __restrict__ v16, __half* __restrict__ y16) {
    extern __shared__ __align__(1024) char sm[];
    const uint32_t sb = smem_u32(sm);

    const int qi = blockIdx.x;
    const int h  = blockIdx.y;
    const int b  = blockIdx.z;
    const int q0 = qi * 128;
    const size_t base = ((size_t)(b * HH + h)) * TT * 64;

    const int tid  = threadIdx.x;
    const int warp = tid >> 5;
    const int lane = tid & 31;
    const int l_sub = lane & 15;
    const int l_cc  = lane >> 4;
    const int lq = lane >> 2;
    const int lr = lane & 3;

    const int nt = 2 * qi + 2;
    auto load_kv = [&](int s, int k0) {
        const uint32_t st = sb + Q_BYTES + s * KV_STAGE_B;
        const size_t srcb = base + (size_t)k0 * 64;
        #pragma unroll
        for (int t2 = 0; t2 < 2; t2++) {
            const int idx = tid + t2 * 256;
            const int row = idx >> 3, ch = idx & 7;
            const uint32_t off = row * AP + ch * 16;
            const size_t g = srcb + (size_t)row * 64 + ch * 8;
            cp16(st + off, k16 + g);
            cp16(st + KV_TILE_B + off, v16 + g);
        }
    };

    #pragma unroll
    for (int t2 = 0; t2 < 4; t2++) {
        const int idx = tid + t2 * 256;
        const int row = idx >> 3, ch = idx & 7;
        cp16(sb + row * AP + ch * 16, q16 + base + (size_t)(q0 + row) * 64 + ch * 8);
    }
    load_kv(0, 0);
    CP_COMMIT();
    if (nt > 1) load_kv(1, 64);
    CP_COMMIT();

    CP_WAIT1();
    __syncthreads();

    uint32_t aq[4][4];
    #pragma unroll
    for (int kk = 0; kk < 4; kk++)
        ldsm4(aq[kk], sb + (warp * 16 + l_sub) * AP + (kk * 2 + l_cc) * 16);

    float m0r = -1e30f, m1r = -1e30f, l0 = 0.f, l1 = 0.f;
    float o[8][4];
    #pragma unroll
    for (int j = 0; j < 8; j++)
        #pragma unroll
        for (int r = 0; r < 4; r++) o[j][r] = 0.f;

    const int r0g = q0 + warp * 16 + lq;
    const int r1g = r0g + 8;
    const int rowmaxw = q0 + warp * 16 + 15;

    int slot = 0;
    for (int kt = 0; kt < nt; kt++) {
        const int k0 = kt * 64;
        if (kt > 0) {
            CP_WAIT1();
            __syncthreads();
        }

        if (kt + 2 < nt) {
            const int ns = (slot + 2 >= 3) ? slot - 1 : slot + 2;
            load_kv(ns, (kt + 2) * 64);
        }
        CP_COMMIT();

        if (k0 <= rowmaxw) {
            const uint32_t st = sb + Q_BYTES + slot * KV_STAGE_B;

            float s[8][4];
            #pragma unroll
            for (int j = 0; j < 8; j++)
                #pragma unroll
                for (int r = 0; r < 4; r++) s[j][r] = 0.f;

            #pragma unroll
            for (int kk = 0; kk < 4; kk++) {
                uint32_t bk[8][2];
                #pragma unroll
                for (int j2 = 0; j2 < 4; j2++) {
                    uint32_t r[4];
                    ldsm4(r, st + (j2 * 16 + l_sub) * AP + (kk * 2 + l_cc) * 16);
                    bk[j2 * 2][0] = r[0];     bk[j2 * 2][1] = r[2];
                    bk[j2 * 2 + 1][0] = r[1]; bk[j2 * 2 + 1][1] = r[3];
                }
                #pragma unroll
                for (int j = 0; j < 8; j++) mma16816(s[j], aq[kk], bk[j]);
            }

            if (k0 + 63 > q0 + warp * 16) {
                #pragma unroll
                for (int j = 0; j < 8; j++) {
                    const int c = k0 + 8 * j + 2 * lr;
                    if (c > r0g)     s[j][0] = -1e30f;
                    if (c + 1 > r0g) s[j][1] = -1e30f;
                    if (c > r1g)     s[j][2] = -1e30f;
                    if (c + 1 > r1g) s[j][3] = -1e30f;
                }
            }

            float mx0 = -1e30f, mx1 = -1e30f;
            #pragma unroll
            for (int j = 0; j < 8; j++) {
                mx0 = fmaxf(mx0, fmaxf(s[j][0], s[j][1]));
                mx1 = fmaxf(mx1, fmaxf(s[j][2], s[j][3]));
            }
            #pragma unroll
            for (int off = 1; off <= 2; off <<= 1) {
                mx0 = fmaxf(mx0, __shfl_xor_sync(0xffffffffu, mx0, off));
                mx1 = fmaxf(mx1, __shfl_xor_sync(0xffffffffu, mx1, off));
            }
            const float mn0 = fmaxf(m0r, mx0), mn1 = fmaxf(m1r, mx1);
            const float c0 = __expf(m0r - mn0), c1 = __expf(m1r - mn1);
            m0r = mn0; m1r = mn1;

            float rs0 = 0.f, rs1 = 0.f;
            #pragma unroll
            for (int j = 0; j < 8; j++) {
                s[j][0] = __expf(s[j][0] - mn0);
                s[j][1] = __expf(s[j][1] - mn0);
                s[j][2] = __expf(s[j][2] - mn1);
                s[j][3] = __expf(s[j][3] - mn1);
                rs0 += s[j][0] + s[j][1];
                rs1 += s[j][2] + s[j][3];
            }
            #pragma unroll
            for (int off = 1; off <= 2; off <<= 1) {
                rs0 += __shfl_xor_sync(0xffffffffu, rs0, off);
                rs1 += __shfl_xor_sync(0xffffffffu, rs1, off);
            }
            l0 = l0 * c0 + rs0;
            l1 = l1 * c1 + rs1;
            #pragma unroll
            for (int j = 0; j < 8; j++) {
                o[j][0] *= c0; o[j][1] *= c0;
                o[j][2] *= c1; o[j][3] *= c1;
            }

            #pragma unroll
            for (int kg = 0; kg < 4; kg++) {
                uint32_t ap[4];
                ap[0] = h2pack(s[2 * kg][0], s[2 * kg][1]);
                ap[1] = h2pack(s[2 * kg][2], s[2 * kg][3]);
                ap[2] = h2pack(s[2 * kg + 1][0], s[2 * kg + 1][1]);
                ap[3] = h2pack(s[2 * kg + 1][2], s[2 * kg + 1][3]);

                const int mm = lane >> 3;
                const int rowv = kg * 16 + (mm & 1) * 8 + (lane & 7);
                const int chb = mm >> 1;

                uint32_t bv[8][2];
                #pragma unroll
                for (int dg = 0; dg < 4; dg++) {
                    uint32_t r[4];
                    ldsm4t(r, st + KV_TILE_B + rowv * AP + (dg * 2 + chb) * 16);
                    bv[dg * 2][0] = r[0];     bv[dg * 2][1] = r[1];
                    bv[dg * 2 + 1][0] = r[2]; bv[dg * 2 + 1][1] = r[3];
                }
                #pragma unroll
                for (int jn = 0; jn < 8; jn++) mma16816(o[jn], ap, bv[jn]);
            }
        }

        slot = (slot + 1 == 3) ? 0 : slot + 1;
    }

    const float inv0 = 1.0f / l0;
    const float inv1 = 1.0f / l1;
    const size_t tok0 = (size_t)(b * TT + q0 + warp * 16 + lq);
    const size_t tok1 = tok0 + 8;
    #pragma unroll
    for (int jn = 0; jn < 8; jn++) {
        const int d = 8 * jn + 2 * lr;
        ((uint32_t*)y16)[(tok0 * DD + h * 64 + d) >> 1] = h2pack(o[jn][0] * inv0, o[jn][1] * inv0);
        ((uint32_t*)y16)[(tok1 * DD + h * 64 + d) >> 1] = h2pack(o[jn][2] * inv1, o[jn][3] * inv1);
    }
}

// ---------------------------------------------------------------------------
// Host side
// ---------------------------------------------------------------------------
extern "C" void kernel_launch(void* const* d_in, const int* in_sizes, int n_in,
                              void* d_out, int out_size) {
    const float* x      = (const float*)d_in[0];
    const float* w_qkv  = (const float*)d_in[2];
    const float* b_qkv  = (const float*)d_in[3];
    const float* w_proj = (const float*)d_in[4];
    const float* b_proj = (const float*)d_in[5];
    float* out = (float*)d_out;

    void *px, *pwq, *pwp, *py, *pq, *pk, *pv;
    cudaGetSymbolAddress(&px, g_x16);
    cudaGetSymbolAddress(&pwq, g_wq16);
    cudaGetSymbolAddress(&pwp, g_wp16);
    cudaGetSymbolAddress(&py, g_y16);
    cudaGetSymbolAddress(&pq, g_q16);
    cudaGetSymbolAddress(&pk, g_k16);
    cudaGetSymbolAddress(&pv, g_v16);

    static int attr_set = 0;
    if (!attr_set) {
        cudaFuncSetAttribute(qkv_gemm_kernel,
                             cudaFuncAttributeMaxDynamicSharedMemorySize, GSMEM);
        cudaFuncSetAttribute(proj_gemm_kernel,
                             cudaFuncAttributeMaxDynamicSharedMemorySize, GSMEM);
        cudaFuncSetAttribute(attn_mma_kernel,
                             cudaFuncAttributeMaxDynamicSharedMemorySize, ATT_SMEM);
        attr_set = 1;
    }

    // 1) fused convert: x, w_qkv, w_proj -> fp16 (one launch)
    {
        const int n0 = (MROWS * DD) / 4;
        const int n1 = (3 * DD * DD) / 4;
        const int n2 = (DD * DD) / 4;
        const int total = n0 + n1 + n2;
        convert3_kernel<<<(total + 255) / 256, 256>>>(
            x, (__half*)px, n0, w_qkv, (__half*)pwq, n1, w_proj, (__half*)pwp, n2);
    }

    // 2) QKV GEMM -> q/k/v fp16 in [b,h,t,d] (q pre-scaled by 1/8)
    {
        dim3 grid((3 * DD) / 128, MROWS / 128);
        qkv_gemm_kernel<<<grid, 256, GSMEM>>>(
            (const __half*)px, (const __half*)pwq, b_qkv,
            (__half*)pq, (__half*)pk, (__half*)pv);
    }

    // 3) flash attention (mma.sync fp16) -> y fp16
    {
        dim3 grid(TT / 128, HH, BB);
        attn_mma_kernel<<<grid, 256, ATT_SMEM>>>(
            (const __half*)pq, (const __half*)pk, (const __half*)pv, (__half*)py);
    }

    // 4) output projection -> out (fp32)
    {
        dim3 grid(DD / 128, MROWS / 128);
        proj_gemm_kernel<<<grid, 256, GSMEM>>>(
            (const __half*)py, (const __half*)pwp, b_proj, out, DD);
    }
}

// round 15
// speedup vs baseline: 2.8397x; 1.0141x over previous
#include <cuda_runtime.h>
#include <cuda_fp16.h>
#include <cstdint>
#include <math.h>

#define BB 2
#define TT 2048
#define DD 1024
#define HH 16
#define HDIM 64
#define MROWS (BB * TT)   // 4096

// ---------------------------------------------------------------------------
// Scratch (device globals; no allocation anywhere). All fp16 single-pass.
// ---------------------------------------------------------------------------
__device__ __align__(256) __half g_x16[(size_t)MROWS * DD];
__device__ __align__(256) __half g_wq16[(size_t)3 * DD * DD];
__device__ __align__(256) __half g_wp16[(size_t)DD * DD];
__device__ __align__(256) __half g_y16[(size_t)MROWS * DD];
__device__ __align__(256) __half g_q16[(size_t)MROWS * DD];
__device__ __align__(256) __half g_k16[(size_t)MROWS * DD];
__device__ __align__(256) __half g_v16[(size_t)MROWS * DD];

// ---------------------------------------------------------------------------
// helpers
// ---------------------------------------------------------------------------
__device__ __forceinline__ uint32_t smem_u32(const void* p) {
    uint32_t a;
    asm("{ .reg .u64 t; cvta.to.shared.u64 t, %1; cvt.u32.u64 %0, t; }"
        : "=r"(a) : "l"(p));
    return a;
}
__device__ __forceinline__ void cp16(uint32_t d, const void* g) {
    asm volatile("cp.async.cg.shared.global [%0], [%1], 16;" :: "r"(d), "l"(g));
}
__device__ __forceinline__ void ldsm4(uint32_t* r, uint32_t a) {
    asm volatile("ldmatrix.sync.aligned.m8n8.x4.shared.b16 {%0,%1,%2,%3}, [%4];"
        : "=r"(r[0]), "=r"(r[1]), "=r"(r[2]), "=r"(r[3]) : "r"(a));
}
__device__ __forceinline__ void ldsm4t(uint32_t* r, uint32_t a) {
    asm volatile("ldmatrix.sync.aligned.m8n8.x4.trans.shared.b16 {%0,%1,%2,%3}, [%4];"
        : "=r"(r[0]), "=r"(r[1]), "=r"(r[2]), "=r"(r[3]) : "r"(a));
}
__device__ __forceinline__ void mma16816(float* c, const uint32_t* a, const uint32_t* b) {
    asm volatile("mma.sync.aligned.m16n8k16.row.col.f32.f16.f16.f32 "
        "{%0,%1,%2,%3}, {%4,%5,%6,%7}, {%8,%9}, {%0,%1,%2,%3};"
        : "+f"(c[0]), "+f"(c[1]), "+f"(c[2]), "+f"(c[3])
        : "r"(a[0]), "r"(a[1]), "r"(a[2]), "r"(a[3]), "r"(b[0]), "r"(b[1]));
}
__device__ __forceinline__ uint32_t h2pack(float a, float b) {
    __half2 h = __floats2half2_rn(a, b);
    return *(uint32_t*)&h;
}
__device__ __forceinline__ float ex2(float x) {
    float r; asm("ex2.approx.f32 %0, %1;" : "=f"(r) : "f"(x)); return r;
}
#define CP_COMMIT() asm volatile("cp.async.commit_group;" ::: "memory")
#define CP_WAIT1()  asm volatile("cp.async.wait_group 1;" ::: "memory")
#define CP_WAIT3()  asm volatile("cp.async.wait_group 3;" ::: "memory")

// ---------------------------------------------------------------------------
// fused fp32 -> fp16 convert for x, w_qkv, w_proj in one launch
// ---------------------------------------------------------------------------
__global__ __launch_bounds__(256) void convert3_kernel(
    const float* __restrict__ i0, __half* __restrict__ o0, int n0,
    const float* __restrict__ i1, __half* __restrict__ o1, int n1,
    const float* __restrict__ i2, __half* __restrict__ o2, int n2) {
    int i = blockIdx.x * blockDim.x + threadIdx.x;
    const float* in; __half* out; int j;
    if (i < n0) { in = i0; out = o0; j = i; }
    else if (i < n0 + n1) { in = i1; out = o1; j = i - n0; }
    else if (i < n0 + n1 + n2) { in = i2; out = o2; j = i - n0 - n1; }
    else return;
    float4 v = ((const float4*)in)[j];
    ((uint32_t*)out)[2 * j]     = h2pack(v.x, v.y);
    ((uint32_t*)out)[2 * j + 1] = h2pack(v.z, v.w);
}

// ---------------------------------------------------------------------------
// Single-pass fp16 GEMM (R14-validated; at the fp32-acc HMMA HW ceiling).
// BK=32 stages, 2-rows-per-144B packed pitch, 6-slot ring, 4 in flight,
// barrier every other iteration. 110.6KB/CTA, 2 CTA/SM, 32 iterations.
// ---------------------------------------------------------------------------
#define GTILE2 (64 * 144)        // 9216
#define GSTAGE2 (2 * GTILE2)     // 18432
#define GSLOTS 6
#define GSMEM (GSLOTS * GSTAGE2) // 110592
#define GNIT2 32

__device__ __forceinline__ uint32_t g_off(int row, int ch) {
    return (uint32_t)((row >> 1) * 144 + (row & 1) * 64 + ch * 16);
}

__device__ __forceinline__ void load_stage2(uint32_t st,
                                            const __half* __restrict__ A,
                                            const __half* __restrict__ B,
                                            int m0, int n0, int kk, int tid) {
    #pragma unroll
    for (int t = 0; t < 2; t++) {
        const int idx = tid + t * 256;
        const int row = idx >> 2;
        const int ch  = idx & 3;
        const uint32_t off = g_off(row, ch);
        cp16(st + off,          A + (size_t)(m0 + row) * DD + kk + ch * 8);
        cp16(st + GTILE2 + off, B + (size_t)(n0 + row) * DD + kk + ch * 8);
    }
}

__device__ __forceinline__ void gemm_mainloop(uint32_t sbase,
                                              const __half* __restrict__ A,
                                              const __half* __restrict__ B,
                                              int m0, int n0, int tid,
                                              float (&acc)[2][8][4]) {
    const int lane = tid & 31;
    const int warp = tid >> 5;
    const int wm = warp >> 1;
    const int wn = warp & 1;
    const int l_sub = lane & 15;
    const int l_cc  = lane >> 4;

    #pragma unroll
    for (int s = 0; s < 4; s++) {
        load_stage2(sbase + s * GSTAGE2, A, B, m0, n0, s * 32, tid);
        CP_COMMIT();
    }

    int slot = 0;
    for (int it = 0; it < GNIT2; it++) {
        CP_WAIT3();
        if ((it & 1) == 0) __syncthreads();

        if (it + 4 < GNIT2) {
            int ns = slot + 4; if (ns >= GSLOTS) ns -= GSLOTS;
            load_stage2(sbase + ns * GSTAGE2, A, B, m0, n0, (it + 4) * 32, tid);
        }
        CP_COMMIT();

        const uint32_t st = sbase + slot * GSTAGE2;

        #pragma unroll
        for (int h = 0; h < 2; h++) {
            const int cc = h * 2 + l_cc;
            uint32_t a[2][4], b[8][2];
            #pragma unroll
            for (int i = 0; i < 2; i++)
                ldsm4(a[i], st + g_off(wm * 32 + i * 16 + l_sub, cc));
            #pragma unroll
            for (int j2 = 0; j2 < 4; j2++) {
                uint32_t r[4];
                ldsm4(r, st + GTILE2 + g_off(wn * 64 + j2 * 16 + l_sub, cc));
                b[j2 * 2][0] = r[0];     b[j2 * 2][1] = r[2];
                b[j2 * 2 + 1][0] = r[1]; b[j2 * 2 + 1][1] = r[3];
            }
            #pragma unroll
            for (int i = 0; i < 2; i++)
                #pragma unroll
                for (int j = 0; j < 8; j++)
                    mma16816(acc[i][j], a[i], b[j]);
        }

        slot = (slot + 1 == GSLOTS) ? 0 : slot + 1;
    }
}

// ---- qkv GEMM: scatter epilogue -> q/k/v fp16 in [b,h,t,d] ----
// q pre-scaled by 0.125 * log2(e) so attention can use ex2 directly.
__global__ __launch_bounds__(256, 2)
void qkv_gemm_kernel(const __half* __restrict__ A,
                     const __half* __restrict__ B,
                     const float* __restrict__ bias,
                     __half* __restrict__ q16, __half* __restrict__ k16,
                     __half* __restrict__ v16) {
    extern __shared__ __align__(1024) char sm[];
    const uint32_t sbase = smem_u32(sm);
    const int tid = threadIdx.x;
    const int lane = tid & 31;
    const int warp = tid >> 5;
    const int wm = warp >> 1, wn = warp & 1;
    const int m0 = blockIdx.y * 128;
    const int n0 = blockIdx.x * 128;

    float acc[2][8][4];
    #pragma unroll
    for (int i = 0; i < 2; i++)
        #pragma unroll
        for (int j = 0; j < 8; j++)
            #pragma unroll
            for (int r = 0; r < 4; r++) acc[i][j][r] = 0.f;

    gemm_mainloop(sbase, A, B, m0, n0, tid, acc);

    const float QSCALE = 0.125f * 1.4426950408889634f;  // 1/sqrt(64) * log2(e)
    const int l4 = lane >> 2;
    const int l2 = (lane & 3) << 1;
    #pragma unroll
    for (int i = 0; i < 2; i++) {
        const int row = m0 + wm * 32 + i * 16 + l4;
        const int bi = row >> 11;
        const int t  = row & 2047;
        #pragma unroll
        for (int j = 0; j < 8; j++) {
            const int col = n0 + wn * 64 + j * 8 + l2;
            const int type = col >> 10;
            const int hc = (col & 1023) >> 6;
            const int d  = col & 63;
            const float2 bv = *(const float2*)(bias + col);
            float v0 = acc[i][j][0] + bv.x, v1 = acc[i][j][1] + bv.y;
            float v2 = acc[i][j][2] + bv.x, v3 = acc[i][j][3] + bv.y;
            if (type == 0) { v0 *= QSCALE; v1 *= QSCALE; v2 *= QSCALE; v3 *= QSCALE; }
            __half* dst = (type == 0) ? q16 : (type == 1) ? k16 : v16;
            const size_t off0 = (((size_t)(bi * HH + hc)) * TT + t) * 64 + d;
            const size_t off1 = off0 + 8 * 64;
            ((uint32_t*)dst)[off0 >> 1] = h2pack(v0, v1);
            ((uint32_t*)dst)[off1 >> 1] = h2pack(v2, v3);
        }
    }
}

// ---- proj GEMM: fp32 epilogue ----
__global__ __launch_bounds__(256, 2)
void proj_gemm_kernel(const __half* __restrict__ A,
                      const __half* __restrict__ B,
                      const float* __restrict__ bias,
                      float* __restrict__ C, int ldc) {
    extern __shared__ __align__(1024) char sm[];
    const uint32_t sbase = smem_u32(sm);
    const int tid = threadIdx.x;
    const int lane = tid & 31;
    const int warp = tid >> 5;
    const int wm = warp >> 1, wn = warp & 1;
    const int m0 = blockIdx.y * 128;
    const int n0 = blockIdx.x * 128;

    float acc[2][8][4];
    #pragma unroll
    for (int i = 0; i < 2; i++)
        #pragma unroll
        for (int j = 0; j < 8; j++)
            #pragma unroll
            for (int r = 0; r < 4; r++) acc[i][j][r] = 0.f;

    gemm_mainloop(sbase, A, B, m0, n0, tid, acc);

    const int l4 = lane >> 2;
    const int l2 = (lane & 3) << 1;
    #pragma unroll
    for (int i = 0; i < 2; i++) {
        const int row0 = m0 + wm * 32 + i * 16 + l4;
        #pragma unroll
        for (int j = 0; j < 8; j++) {
            const int col = n0 + wn * 64 + j * 8 + l2;
            const float2 bv = *(const float2*)(bias + col);
            float2 v0, v1;
            v0.x = acc[i][j][0] + bv.x; v0.y = acc[i][j][1] + bv.y;
            v1.x = acc[i][j][2] + bv.x; v1.y = acc[i][j][3] + bv.y;
            *(float2*)(C + (size_t)row0 * ldc + col) = v0;
            *(float2*)(C + (size_t)(row0 + 8) * ldc + col) = v1;
        }
    }
}

// ---------------------------------------------------------------------------
// Flash attention on mma.sync, single-pass fp16.
// CTA = 128 q rows x (head, batch), 256 threads. qi REVERSED (long CTAs
// first). kv staged 128 rows at a time (K then V), 2-slot ring; each stage
// processed as two 64-sub-tiles with per-subtile warp skip. ex2-based
// softmax (log2e folded into q). smem 92.2KB -> 2 CTA/SM.
// ---------------------------------------------------------------------------
#define AP 144
#define Q_BYTES (128 * AP)             // 18432
#define K128_B (128 * AP)              // 18432
#define KV_STAGE_B (2 * K128_B)        // 36864 (K128 + V128)
#define ATT_SMEM (Q_BYTES + 2 * KV_STAGE_B)  // 92160

__global__ __launch_bounds__(256, 2)
void attn_mma_kernel(const __half* __restrict__ q16, const __half* __restrict__ k16,
                     const __half* __restrict__ v16, __half* __restrict__ y16) {
    extern __shared__ __align__(1024) char sm[];
    const uint32_t sb = smem_u32(sm);

    const int qi = (int)gridDim.x - 1 - (int)blockIdx.x;   // reversed: long first
    const int h  = blockIdx.y;
    const int b  = blockIdx.z;
    const int q0 = qi * 128;
    const size_t base = ((size_t)(b * HH + h)) * TT * 64;

    const int tid  = threadIdx.x;
    const int warp = tid >> 5;
    const int lane = tid & 31;
    const int l_sub = lane & 15;
    const int l_cc  = lane >> 4;
    const int lq = lane >> 2;
    const int lr = lane & 3;

    const int ntt = qi + 1;   // 128-wide k tiles
    auto load_kv = [&](int s, int k0) {
        const uint32_t st = sb + Q_BYTES + s * KV_STAGE_B;
        const size_t srcb = base + (size_t)k0 * 64;
        #pragma unroll
        for (int t2 = 0; t2 < 4; t2++) {
            const int idx = tid + t2 * 256;   // 0..1023 (128 rows x 8 chunks)
            const int row = idx >> 3, ch = idx & 7;
            const uint32_t off = row * AP + ch * 16;
            const size_t g = srcb + (size_t)row * 64 + ch * 8;
            cp16(st + off, k16 + g);
            cp16(st + K128_B + off, v16 + g);
        }
    };

    // prologue: group0 = Q + kv tile 0; group1 = kv tile 1 (if any)
    #pragma unroll
    for (int t2 = 0; t2 < 4; t2++) {
        const int idx = tid + t2 * 256;
        const int row = idx >> 3, ch = idx & 7;
        cp16(sb + row * AP + ch * 16, q16 + base + (size_t)(q0 + row) * 64 + ch * 8);
    }
    load_kv(0, 0);
    CP_COMMIT();
    if (ntt > 1) load_kv(1, 128);
    CP_COMMIT();

    CP_WAIT1();
    __syncthreads();

    uint32_t aq[4][4];
    #pragma unroll
    for (int kk = 0; kk < 4; kk++)
        ldsm4(aq[kk], sb + (warp * 16 + l_sub) * AP + (kk * 2 + l_cc) * 16);

    float m0r = -1e30f, m1r = -1e30f, l0 = 0.f, l1 = 0.f;
    float o[8][4];
    #pragma unroll
    for (int j = 0; j < 8; j++)
        #pragma unroll
        for (int r = 0; r < 4; r++) o[j][r] = 0.f;

    const int r0g = q0 + warp * 16 + lq;
    const int r1g = r0g + 8;
    const int rowmaxw = q0 + warp * 16 + 15;

    for (int kt = 0; kt < ntt; kt++) {
        if (kt > 0) {
            CP_WAIT1();
            __syncthreads();
        }
        const uint32_t stg = sb + Q_BYTES + (kt & 1) * KV_STAGE_B;

        #pragma unroll
        for (int sub = 0; sub < 2; sub++) {
            const int k0 = kt * 128 + sub * 64;
            if (k0 > rowmaxw) continue;   // warp fully above diagonal
            const uint32_t stK = stg + sub * 64 * AP;
            const uint32_t stV = stg + K128_B + sub * 64 * AP;

            // ---- S = Q K^T ----
            float s[8][4];
            #pragma unroll
            for (int j = 0; j < 8; j++)
                #pragma unroll
                for (int r = 0; r < 4; r++) s[j][r] = 0.f;

            #pragma unroll
            for (int kk = 0; kk < 4; kk++) {
                uint32_t bk[8][2];
                #pragma unroll
                for (int j2 = 0; j2 < 4; j2++) {
                    uint32_t r[4];
                    ldsm4(r, stK + (j2 * 16 + l_sub) * AP + (kk * 2 + l_cc) * 16);
                    bk[j2 * 2][0] = r[0];     bk[j2 * 2][1] = r[2];
                    bk[j2 * 2 + 1][0] = r[1]; bk[j2 * 2 + 1][1] = r[3];
                }
                #pragma unroll
                for (int j = 0; j < 8; j++) mma16816(s[j], aq[kk], bk[j]);
            }

            // ---- causal mask (diagonal sub-tiles) ----
            if (k0 + 63 > q0 + warp * 16) {
                #pragma unroll
                for (int j = 0; j < 8; j++) {
                    const int c = k0 + 8 * j + 2 * lr;
                    if (c > r0g)     s[j][0] = -1e30f;
                    if (c + 1 > r0g) s[j][1] = -1e30f;
                    if (c > r1g)     s[j][2] = -1e30f;
                    if (c + 1 > r1g) s[j][3] = -1e30f;
                }
            }

            // ---- online softmax (base-2 domain) ----
            float mx0 = -1e30f, mx1 = -1e30f;
            #pragma unroll
            for (int j = 0; j < 8; j++) {
                mx0 = fmaxf(mx0, fmaxf(s[j][0], s[j][1]));
                mx1 = fmaxf(mx1, fmaxf(s[j][2], s[j][3]));
            }
            #pragma unroll
            for (int off = 1; off <= 2; off <<= 1) {
                mx0 = fmaxf(mx0, __shfl_xor_sync(0xffffffffu, mx0, off));
                mx1 = fmaxf(mx1, __shfl_xor_sync(0xffffffffu, mx1, off));
            }
            const float mn0 = fmaxf(m0r, mx0), mn1 = fmaxf(m1r, mx1);
            const float c0 = ex2(m0r - mn0), c1 = ex2(m1r - mn1);
            m0r = mn0; m1r = mn1;

            float rs0 = 0.f, rs1 = 0.f;
            #pragma unroll
            for (int j = 0; j < 8; j++) {
                s[j][0] = ex2(s[j][0] - mn0);
                s[j][1] = ex2(s[j][1] - mn0);
                s[j][2] = ex2(s[j][2] - mn1);
                s[j][3] = ex2(s[j][3] - mn1);
                rs0 += s[j][0] + s[j][1];
                rs1 += s[j][2] + s[j][3];
            }
            #pragma unroll
            for (int off = 1; off <= 2; off <<= 1) {
                rs0 += __shfl_xor_sync(0xffffffffu, rs0, off);
                rs1 += __shfl_xor_sync(0xffffffffu, rs1, off);
            }
            l0 = l0 * c0 + rs0;
            l1 = l1 * c1 + rs1;
            #pragma unroll
            for (int j = 0; j < 8; j++) {
                o[j][0] *= c0; o[j][1] *= c0;
                o[j][2] *= c1; o[j][3] *= c1;
            }

            // ---- O += P V ----
            #pragma unroll
            for (int kg = 0; kg < 4; kg++) {
                uint32_t ap[4];
                ap[0] = h2pack(s[2 * kg][0], s[2 * kg][1]);
                ap[1] = h2pack(s[2 * kg][2], s[2 * kg][3]);
                ap[2] = h2pack(s[2 * kg + 1][0], s[2 * kg + 1][1]);
                ap[3] = h2pack(s[2 * kg + 1][2], s[2 * kg + 1][3]);

                const int mm = lane >> 3;
                const int rowv = kg * 16 + (mm & 1) * 8 + (lane & 7);
                const int chb = mm >> 1;

                uint32_t bv[8][2];
                #pragma unroll
                for (int dg = 0; dg < 4; dg++) {
                    uint32_t r[4];
                    ldsm4t(r, stV + rowv * AP + (dg * 2 + chb) * 16);
                    bv[dg * 2][0] = r[0];     bv[dg * 2][1] = r[1];
                    bv[dg * 2 + 1][0] = r[2]; bv[dg * 2 + 1][1] = r[3];
                }
                #pragma unroll
                for (int jn = 0; jn < 8; jn++) mma16816(o[jn], ap, bv[jn]);
            }
        }

        __syncthreads();   // stage consumed by all warps before refill
        if (kt + 2 < ntt) load_kv(kt & 1, (kt + 2) * 128);
        CP_COMMIT();
    }

    const float inv0 = 1.0f / l0;
    const float inv1 = 1.0f / l1;
    const size_t tok0 = (size_t)(b * TT + q0 + warp * 16 + lq);
    const size_t tok1 = tok0 + 8;
    #pragma unroll
    for (int jn = 0; jn < 8; jn++) {
        const int d = 8 * jn + 2 * lr;
        ((uint32_t*)y16)[(tok0 * DD + h * 64 + d) >> 1] = h2pack(o[jn][0] * inv0, o[jn][1] * inv0);
        ((uint32_t*)y16)[(tok1 * DD + h * 64 + d) >> 1] = h2pack(o[jn][2] * inv1, o[jn][3] * inv1);
    }
}

// ---------------------------------------------------------------------------
// Host side
// ---------------------------------------------------------------------------
extern "C" void kernel_launch(void* const* d_in, const int* in_sizes, int n_in,
                              void* d_out, int out_size) {
    const float* x      = (const float*)d_in[0];
    const float* w_qkv  = (const float*)d_in[2];
    const float* b_qkv  = (const float*)d_in[3];
    const float* w_proj = (const float*)d_in[4];
    const float* b_proj = (const float*)d_in[5];
    float* out = (float*)d_out;

    void *px, *pwq, *pwp, *py, *pq, *pk, *pv;
    cudaGetSymbolAddress(&px, g_x16);
    cudaGetSymbolAddress(&pwq, g_wq16);
    cudaGetSymbolAddress(&pwp, g_wp16);
    cudaGetSymbolAddress(&py, g_y16);
    cudaGetSymbolAddress(&pq, g_q16);
    cudaGetSymbolAddress(&pk, g_k16);
    cudaGetSymbolAddress(&pv, g_v16);

    static int attr_set = 0;
    if (!attr_set) {
        cudaFuncSetAttribute(qkv_gemm_kernel,
                             cudaFuncAttributeMaxDynamicSharedMemorySize, GSMEM);
        cudaFuncSetAttribute(proj_gemm_kernel,
                             cudaFuncAttributeMaxDynamicSharedMemorySize, GSMEM);
        cudaFuncSetAttribute(attn_mma_kernel,
                             cudaFuncAttributeMaxDynamicSharedMemorySize, ATT_SMEM);
        attr_set = 1;
    }

    // 1) fused convert: x, w_qkv, w_proj -> fp16 (one launch)
    {
        const int n0 = (MROWS * DD) / 4;
        const int n1 = (3 * DD * DD) / 4;
        const int n2 = (DD * DD) / 4;
        const int total = n0 + n1 + n2;
        convert3_kernel<<<(total + 255) / 256, 256>>>(
            x, (__half*)px, n0, w_qkv, (__half*)pwq, n1, w_proj, (__half*)pwp, n2);
    }

    // 2) QKV GEMM -> q/k/v fp16 in [b,h,t,d] (q pre-scaled by log2e/8)
    {
        dim3 grid((3 * DD) / 128, MROWS / 128);
        qkv_gemm_kernel<<<grid, 256, GSMEM>>>(
            (const __half*)px, (const __half*)pwq, b_qkv,
            (__half*)pq, (__half*)pk, (__half*)pv);
    }

    // 3) flash attention (mma.sync fp16, reversed qi) -> y fp16
    {
        dim3 grid(TT / 128, HH, BB);
        attn_mma_kernel<<<grid, 256, ATT_SMEM>>>(
            (const __half*)pq, (const __half*)pk, (const __half*)pv, (__half*)py);
    }

    // 4) output projection -> out (fp32)
    {
        dim3 grid(DD / 128, MROWS / 128);
        proj_gemm_kernel<<<grid, 256, GSMEM>>>(
            (const __half*)py, (const __half*)pwp, b_proj, out, DD);
    }
}